// round 12
// baseline (speedup 1.0000x reference)
#include <cuda_runtime.h>
#include <cuda_bf16.h>
#include <math.h>
#include <stdint.h>

#define NL 3
#define DD 512
#define NV 100
#define NB 128
#define NS 512
#define NSE 512
#define MALL (NB*NS)
#define D3 (3*DD)

// ---------------- scratch ----------------
__device__ float g_xp[(size_t)MALL * D3];
__device__ float g_G[NB * D3];
__device__ float g_h[NB * DD];
__device__ float g_mask[MALL];
__device__ unsigned g_cnt4[4];
__device__ volatile unsigned g_gen4[4];
__device__ __nv_bfloat16 g_hsh[NB * DD];
__device__ __nv_bfloat16 g_hsl[NB * DD];
__device__ __nv_bfloat16 g_Ah[(size_t)MALL * DD];
__device__ __nv_bfloat16 g_Al[(size_t)MALL * DD];
__device__ __nv_bfloat16 g_Ph[(size_t)MALL * NSE];
__device__ __nv_bfloat16 g_Pl[(size_t)MALL * NSE];
__device__ __nv_bfloat16 g_Ch[(size_t)MALL * DD];
__device__ __nv_bfloat16 g_Cl[(size_t)MALL * DD];
__device__ __nv_bfloat16 g_Dh[(size_t)MALL * DD];
__device__ __nv_bfloat16 g_Dl[(size_t)MALL * DD];
__device__ __nv_bfloat16 g_ench[(size_t)NB * NSE * DD];
__device__ __nv_bfloat16 g_encl[(size_t)NB * NSE * DD];
__device__ __nv_bfloat16 g_encTh[(size_t)NB * DD * NSE];
__device__ __nv_bfloat16 g_encTl[(size_t)NB * DD * NSE];
__device__ __nv_bfloat16 g_wihh[(size_t)NL * D3 * DD];
__device__ __nv_bfloat16 g_wihl[(size_t)NL * D3 * DD];
__device__ __nv_bfloat16 g_whhh[(size_t)NL * D3 * DD];
__device__ __nv_bfloat16 g_whhl[(size_t)NL * D3 * DD];
__device__ __nv_bfloat16 g_awh[(size_t)DD * 2 * DD];
__device__ __nv_bfloat16 g_awl[(size_t)DD * 2 * DD];
__device__ __nv_bfloat16 g_owh[128 * DD];
__device__ __nv_bfloat16 g_owl[128 * DD];

extern __shared__ float smf[];

// ---------------- helpers ----------------
__device__ __forceinline__ float tanh_fast(float x) {
    float y;
    asm("tanh.approx.f32 %0, %1;" : "=f"(y) : "f"(x));
    return y;
}
__device__ __forceinline__ float sigmoid_fast(float x) { return 1.0f / (1.0f + __expf(-x)); }
__device__ __forceinline__ uint32_t smem_u32(const void* p) {
    uint32_t a;
    asm("{ .reg .u64 t; cvta.to.shared.u64 t, %1; cvt.u32.u64 %0, t; }" : "=r"(a) : "l"(p));
    return a;
}
__device__ __forceinline__ unsigned bfu(__nv_bfloat16 b) {
    unsigned short s = __bfloat16_as_ushort(b);
    return (unsigned)s;
}
__device__ __forceinline__ void split_store(float4 v, __nv_bfloat16* h, __nv_bfloat16* l, size_t i4) {
    __nv_bfloat16 h0 = __float2bfloat16_rn(v.x), h1 = __float2bfloat16_rn(v.y);
    __nv_bfloat16 h2 = __float2bfloat16_rn(v.z), h3 = __float2bfloat16_rn(v.w);
    uint2 hv, lv;
    hv.x = bfu(h0) | (bfu(h1) << 16); hv.y = bfu(h2) | (bfu(h3) << 16);
    lv.x = bfu(__float2bfloat16_rn(v.x - __bfloat162float(h0))) |
           (bfu(__float2bfloat16_rn(v.y - __bfloat162float(h1))) << 16);
    lv.y = bfu(__float2bfloat16_rn(v.z - __bfloat162float(h2))) |
           (bfu(__float2bfloat16_rn(v.w - __bfloat162float(h3))) << 16);
    ((uint2*)h)[i4] = hv; ((uint2*)l)[i4] = lv;
}

// ---------------- mma.sync primitives ----------------
__device__ __forceinline__ void mma16816(float* d, const uint32_t* a, const uint32_t* b) {
    asm volatile(
        "mma.sync.aligned.m16n8k16.row.col.f32.bf16.bf16.f32 "
        "{%0,%1,%2,%3}, {%4,%5,%6,%7}, {%8,%9}, {%0,%1,%2,%3};"
        : "+f"(d[0]), "+f"(d[1]), "+f"(d[2]), "+f"(d[3])
        : "r"(a[0]), "r"(a[1]), "r"(a[2]), "r"(a[3]), "r"(b[0]), "r"(b[1]));
}
__device__ __forceinline__ void ldsm_x4(uint32_t* r, uint32_t addr) {
    asm volatile("ldmatrix.sync.aligned.m8n8.x4.shared.b16 {%0,%1,%2,%3}, [%4];"
        : "=r"(r[0]), "=r"(r[1]), "=r"(r[2]), "=r"(r[3]) : "r"(addr));
}
__device__ __forceinline__ void cpasync16(uint32_t dst, const void* src, int sz) {
    asm volatile("cp.async.ca.shared.global [%0], [%1], 16, %2;" :: "r"(dst), "l"(src), "r"(sz) : "memory");
}
#define CP_COMMIT() asm volatile("cp.async.commit_group;" ::: "memory")
#define CP_WAIT1()  asm volatile("cp.async.wait_group 1;" ::: "memory")
#define CP_WAIT0()  asm volatile("cp.async.wait_group 0;" ::: "memory")

// ---------------- merged conversions ----------------
#define S0 589824u              /* w_ih f4 */
#define S1 (S0 + 589824u)       /* + w_hh */
#define S2 (S1 + 131072u)       /* + attnw */
#define S3 (S2 + 8388608u)      /* + enc */
#define S4 (S3 + 16384u)        /* + outw(padded) */
__global__ void convert_all(
    const float* __restrict__ w_ih, const float* __restrict__ w_hh,
    const float* __restrict__ attnw, const float* __restrict__ outw,
    const float* __restrict__ enc,
    __nv_bfloat16* __restrict__ wihh, __nv_bfloat16* __restrict__ wihl,
    __nv_bfloat16* __restrict__ whhh, __nv_bfloat16* __restrict__ whhl,
    __nv_bfloat16* __restrict__ awh,  __nv_bfloat16* __restrict__ awl,
    __nv_bfloat16* __restrict__ owh,  __nv_bfloat16* __restrict__ owl,
    __nv_bfloat16* __restrict__ ench, __nv_bfloat16* __restrict__ encl)
{
    unsigned i = blockIdx.x * 256 + threadIdx.x;
    if (i >= S4) return;
    if (i < S0) {
        split_store(((const float4*)w_ih)[i], wihh, wihl, i);
    } else if (i < S1) {
        unsigned j = i - S0;
        split_store(((const float4*)w_hh)[j], whhh, whhl, j);
    } else if (i < S2) {
        unsigned j = i - S1;
        split_store(((const float4*)attnw)[j], awh, awl, j);
    } else if (i < S3) {
        unsigned j = i - S2;
        split_store(((const float4*)enc)[j], ench, encl, j);
    } else {
        unsigned j = i - S3;              // over 128*512/4
        unsigned r = j >> 7;              // row (128 f4 per row)
        float4 v = make_float4(0.f, 0.f, 0.f, 0.f);
        if (r < NV) v = ((const float4*)outw)[j];
        split_store(v, owh, owl, j);
    }
}

__global__ void transpose_split_kernel(const float* __restrict__ enc,
                                       __nv_bfloat16* __restrict__ th, __nv_bfloat16* __restrict__ tl) {
    __shared__ float tile[32][33];
    int b = blockIdx.z;
    int d0 = blockIdx.x * 32, s0 = blockIdx.y * 32;
    int x = threadIdx.x, y = threadIdx.y;
    #pragma unroll
    for (int i = 0; i < 32; i += 8)
        tile[y + i][x] = enc[((size_t)b * NSE + s0 + y + i) * DD + d0 + x];
    __syncthreads();
    #pragma unroll
    for (int i = 0; i < 32; i += 8) {
        float v = tile[x][y + i];
        __nv_bfloat16 hb = __float2bfloat16_rn(v);
        size_t o = ((size_t)b * DD + d0 + y + i) * NSE + s0 + x;
        th[o] = hb;
        tl[o] = __float2bfloat16_rn(v - __bfloat162float(hb));
    }
}

__global__ void embed_split_kernel(const int* __restrict__ seqs, const float* __restrict__ emb,
                                   __nv_bfloat16* __restrict__ h, __nv_bfloat16* __restrict__ l) {
    size_t i = (size_t)blockIdx.x * blockDim.x + threadIdx.x;
    size_t row = i >> 7;
    int c = (int)(i & 127);
    int tok = seqs[row];
    split_store(((const float4*)(emb + (size_t)tok * DD))[c], h, l, i);
}
__global__ void copy4_kernel(float* __restrict__ dst, const float* __restrict__ src, int n4) {
    int i = blockIdx.x * blockDim.x + threadIdx.x;
    if (i < n4) ((float4*)dst)[i] = ((const float4*)src)[i];
}
__global__ void h_init_kernel(const float* __restrict__ h0, float* __restrict__ hstate,
                              __nv_bfloat16* __restrict__ hh, __nv_bfloat16* __restrict__ hl) {
    int i = blockIdx.x * 256 + threadIdx.x;
    if (i >= NB * DD / 4) return;
    float4 v = ((const float4*)h0)[i];
    ((float4*)hstate)[i] = v;
    split_store(v, hh, hl, i);
}
__global__ void softmax_kernel(float* __restrict__ P, __nv_bfloat16* __restrict__ ph,
                               __nv_bfloat16* __restrict__ pl) {
    __shared__ float red[256];
    size_t row = blockIdx.x;
    float* p = P + row * NSE;
    int tid = threadIdx.x;
    float v0 = p[tid], v1 = p[tid + 256];
    red[tid] = fmaxf(v0, v1); __syncthreads();
    #pragma unroll
    for (int s = 128; s > 0; s >>= 1) { if (tid < s) red[tid] = fmaxf(red[tid], red[tid + s]); __syncthreads(); }
    float mx = red[0]; __syncthreads();
    float e0 = __expf(v0 - mx), e1 = __expf(v1 - mx);
    red[tid] = e0 + e1; __syncthreads();
    #pragma unroll
    for (int s = 128; s > 0; s >>= 1) { if (tid < s) red[tid] += red[tid + s]; __syncthreads(); }
    float inv = 1.0f / red[0];
    float o0 = e0 * inv, o1 = e1 * inv;
    p[tid] = o0; p[tid + 256] = o1;
    __nv_bfloat16 b0 = __float2bfloat16_rn(o0), b1 = __float2bfloat16_rn(o1);
    ph[row * NSE + tid] = b0;
    ph[row * NSE + tid + 256] = b1;
    pl[row * NSE + tid] = __float2bfloat16_rn(o0 - __bfloat162float(b0));
    pl[row * NSE + tid + 256] = __float2bfloat16_rn(o1 - __bfloat162float(b1));
}

// ---------------- mma.sync split-bf16 NT GEMM, 2-stage, 2 blocks/SM ----------------
// epi: 0 f32(+bias), 2 f32*mask(+bias), 4 bf16-split, 5 tanh*mask bf16-split
#define LDT 40
#define TILE_B (128 * LDT * 2)
#define STAGE_B (4 * TILE_B)         // 40960
#define GM_SMEM (2 * STAGE_B)        // 81920
__global__ void __launch_bounds__(256, 2) gemm_mma(
    const __nv_bfloat16* __restrict__ A0h, const __nv_bfloat16* __restrict__ A0l,
    const __nv_bfloat16* __restrict__ A1h, const __nv_bfloat16* __restrict__ A1l,
    int K0, int K1, int K,
    const __nv_bfloat16* __restrict__ Wh, const __nv_bfloat16* __restrict__ Wl, int nvalid,
    float* __restrict__ C, __nv_bfloat16* __restrict__ Obh, __nv_bfloat16* __restrict__ Obl, int ldc,
    size_t sA, size_t sW, size_t sC,
    float scale, const float* __restrict__ bias, const float* __restrict__ mask, int epi)
{
    uint32_t smb = smem_u32(smf);
    int tid = threadIdx.x, lane = tid & 31, wid = tid >> 5;
    int wm = wid >> 2, wn = wid & 3;
    int bz = blockIdx.z;
    int nBase = blockIdx.x * 128, mBase = blockIdx.y * 128;
    const __nv_bfloat16* a0h = A0h + (size_t)bz * sA;
    const __nv_bfloat16* a0l = A0l + (size_t)bz * sA;
    const __nv_bfloat16* wh  = Wh  + (size_t)bz * sW;
    const __nv_bfloat16* wl  = Wl  + (size_t)bz * sW;
    float* Cb = C + (size_t)bz * sC;
    __nv_bfloat16* obh = Obh + (size_t)bz * sC;
    __nv_bfloat16* obl = Obl + (size_t)bz * sC;

    float acc[4][4][4];
    #pragma unroll
    for (int i = 0; i < 4; i++)
        #pragma unroll
        for (int j = 0; j < 4; j++)
            #pragma unroll
            for (int q = 0; q < 4; q++) acc[i][j][q] = 0.0f;

    auto load_chunk = [&](int buf, int c) {
        int kOff = c * 32;
        const __nv_bfloat16 *ah, *al;
        int lda, ka;
        if (kOff < K0) { ah = a0h; al = a0l; lda = K0; ka = kOff; }
        else           { ah = A1h; al = A1l; lda = K1; ka = kOff - K0; }
        uint32_t sb = smb + buf * STAGE_B;
        #pragma unroll
        for (int p = 0; p < 8; p++) {
            int idx = p * 256 + tid;
            int tile = idx >> 9, rem = idx & 511;
            int r = rem >> 2, c16 = rem & 3;
            uint32_t dst = sb + tile * TILE_B + r * (LDT * 2) + c16 * 16;
            if (tile == 0)      cpasync16(dst, ah + (size_t)(mBase + r) * lda + ka + c16 * 8, 16);
            else if (tile == 1) cpasync16(dst, al + (size_t)(mBase + r) * lda + ka + c16 * 8, 16);
            else if (tile == 2) cpasync16(dst, wh + (size_t)(nBase + r) * K + kOff + c16 * 8, (nBase + r < nvalid) ? 16 : 0);
            else                cpasync16(dst, wl + (size_t)(nBase + r) * K + kOff + c16 * 8, (nBase + r < nvalid) ? 16 : 0);
        }
    };

    int aRow = lane & 15, aK = (lane >> 4) * 8;
    int bRow = (lane & 7) + ((lane >> 4) & 1) * 8, bK = ((lane >> 3) & 1) * 8;

    int nk = K / 32;
    load_chunk(0, 0);
    CP_COMMIT();
    for (int c = 0; c < nk; c++) {
        if (c + 1 < nk) { load_chunk((c + 1) & 1, c + 1); CP_COMMIT(); CP_WAIT1(); }
        else            { CP_WAIT0(); }
        __syncthreads();
        uint32_t sb = smb + (c & 1) * STAGE_B;
        #pragma unroll
        for (int ks = 0; ks < 2; ks++) {
            uint32_t ahf[4][4], alf[4][4];
            #pragma unroll
            for (int mf = 0; mf < 4; mf++) {
                uint32_t ra = sb + ((wm * 64 + mf * 16 + aRow) * LDT + ks * 16 + aK) * 2;
                ldsm_x4(ahf[mf], ra);
                ldsm_x4(alf[mf], ra + TILE_B);
            }
            #pragma unroll
            for (int np = 0; np < 2; np++) {
                uint32_t rb = sb + 2 * TILE_B + ((wn * 32 + np * 16 + bRow) * LDT + ks * 16 + bK) * 2;
                uint32_t bh[4], bl[4];
                ldsm_x4(bh, rb);
                ldsm_x4(bl, rb + TILE_B);
                #pragma unroll
                for (int mf = 0; mf < 4; mf++) {
                    mma16816(acc[mf][np * 2 + 0], ahf[mf], &bh[0]);
                    mma16816(acc[mf][np * 2 + 0], ahf[mf], &bl[0]);
                    mma16816(acc[mf][np * 2 + 0], alf[mf], &bh[0]);
                    mma16816(acc[mf][np * 2 + 1], ahf[mf], &bh[2]);
                    mma16816(acc[mf][np * 2 + 1], ahf[mf], &bl[2]);
                    mma16816(acc[mf][np * 2 + 1], alf[mf], &bh[2]);
                }
            }
        }
        __syncthreads();
    }

    int rOff = lane >> 2, cOff = (lane & 3) * 2;
    #pragma unroll
    for (int mf = 0; mf < 4; mf++) {
        int mrow0 = mBase + wm * 64 + mf * 16 + rOff;
        int mrow1 = mrow0 + 8;
        float mk0 = 1.0f, mk1 = 1.0f;
        if (epi == 2 || epi == 5) {
            mk0 = mask[(size_t)bz * (sC / ldc) + mrow0];
            mk1 = mask[(size_t)bz * (sC / ldc) + mrow1];
        }
        #pragma unroll
        for (int nf = 0; nf < 4; nf++) {
            int col = nBase + wn * 32 + nf * 8 + cOff;
            if (col >= nvalid) continue;
            float v0 = acc[mf][nf][0] * scale, v1 = acc[mf][nf][1] * scale;
            float v2 = acc[mf][nf][2] * scale, v3 = acc[mf][nf][3] * scale;
            if (bias) {
                float b0 = bias[col], b1 = bias[col + 1];
                v0 += b0; v1 += b1; v2 += b0; v3 += b1;
            }
            if (epi == 0) {
                *(float2*)(Cb + (size_t)mrow0 * ldc + col) = make_float2(v0, v1);
                *(float2*)(Cb + (size_t)mrow1 * ldc + col) = make_float2(v2, v3);
            } else if (epi == 2) {
                v0 *= mk0; v1 *= mk0; v2 *= mk1; v3 *= mk1;
                *(float2*)(Cb + (size_t)mrow0 * ldc + col) = make_float2(v0, v1);
                *(float2*)(Cb + (size_t)mrow1 * ldc + col) = make_float2(v2, v3);
            } else {
                if (epi == 5) {
                    v0 = tanh_fast(v0) * mk0; v1 = tanh_fast(v1) * mk0;
                    v2 = tanh_fast(v2) * mk1; v3 = tanh_fast(v3) * mk1;
                }
                __nv_bfloat16 h0 = __float2bfloat16_rn(v0), h1 = __float2bfloat16_rn(v1);
                __nv_bfloat16 h2 = __float2bfloat16_rn(v2), h3 = __float2bfloat16_rn(v3);
                uint32_t hp0 = bfu(h0) | (bfu(h1) << 16);
                uint32_t hp1 = bfu(h2) | (bfu(h3) << 16);
                uint32_t lp0 = bfu(__float2bfloat16_rn(v0 - __bfloat162float(h0))) |
                               (bfu(__float2bfloat16_rn(v1 - __bfloat162float(h1))) << 16);
                uint32_t lp1 = bfu(__float2bfloat16_rn(v2 - __bfloat162float(h2))) |
                               (bfu(__float2bfloat16_rn(v3 - __bfloat162float(h3))) << 16);
                *(uint32_t*)(obh + (size_t)mrow0 * ldc + col) = hp0;
                *(uint32_t*)(obh + (size_t)mrow1 * ldc + col) = hp1;
                *(uint32_t*)(obl + (size_t)mrow0 * ldc + col) = lp0;
                *(uint32_t*)(obl + (size_t)mrow1 * ldc + col) = lp1;
            }
        }
    }
}

// ---------------- per-m-group barrier (24 blocks per group) ----------------
__device__ __forceinline__ void bar4(int grp) {
    __syncthreads();
    if (threadIdx.x == 0) {
        __threadfence();
        unsigned gen = g_gen4[grp];
        unsigned old = atomicAdd(&g_cnt4[grp], 1);
        if (old == 23u) {
            atomicExch(&g_cnt4[grp], 0u);
            __threadfence();
            g_gen4[grp] = gen + 1u;
        } else {
            while (g_gen4[grp] == gen) { }
        }
        __threadfence();
    }
    __syncthreads();
}

// ---------------- persistent tensor-core GRU ----------------
// 96 blocks = 4 m-groups (32 batch rows) x 24 n-tiles (64 W_hh rows). 256 threads (8 warps: 2m x 4n).
#define LDW 520
#define GRUW_B (64 * LDW * 2)        // 66560 bytes per W array
#define GRUH_B (32 * LDW * 2)        // 33280 bytes per h array
#define GRU2_SMEM (2 * GRUW_B + 2 * GRUH_B)   // 199680
__global__ void __launch_bounds__(256, 1) gru_mma(
    const __nv_bfloat16* __restrict__ Wh, const __nv_bfloat16* __restrict__ Wl,
    const float* __restrict__ bhh, const float* __restrict__ xp,
    float* __restrict__ G, float* __restrict__ hstate,
    __nv_bfloat16* __restrict__ hsh, __nv_bfloat16* __restrict__ hsl,
    __nv_bfloat16* __restrict__ yh, __nv_bfloat16* __restrict__ yl,
    float* __restrict__ maskp)
{
    char* sm = (char*)smf;
    uint32_t smb = smem_u32(sm);
    int tid = threadIdx.x, lane = tid & 31, w = tid >> 5;
    int mb = blockIdx.x / 24, nb = blockIdx.x % 24;
    int warp_m = w & 1, warp_n = w >> 1;   // 2 x 4

    // stage W slice (64 rows x 512) hi/lo once
    for (int idx = tid; idx < 64 * 64; idx += 256) {
        int r = idx >> 6, c = idx & 63;
        *(uint4*)(sm + r * (LDW * 2) + c * 16) =
            *(const uint4*)(Wh + (size_t)(nb * 64 + r) * DD + c * 8);
        *(uint4*)(sm + GRUW_B + r * (LDW * 2) + c * 16) =
            *(const uint4*)(Wl + (size_t)(nb * 64 + r) * DD + c * 8);
    }

    int aRow = lane & 15, aK = (lane >> 4) * 8;
    int bRow = (lane & 7) + ((lane >> 4) & 1) * 8, bK = ((lane >> 3) & 1) * 8;
    uint32_t wb_h = smb + ((warp_n * 16 + bRow) * LDW + bK) * 2;
    uint32_t wb_l = wb_h + GRUW_B;
    uint32_t hb_h = smb + 2 * GRUW_B + ((warp_m * 16 + aRow) * LDW + aK) * 2;
    uint32_t hb_l = hb_h + GRUH_B;

    for (int t = 0; t < NS; t++) {
        // stage h tile (32 rows x 512, hi+lo)
        for (int idx = tid; idx < 32 * 64; idx += 256) {
            int r = idx >> 6, c = idx & 63;
            *(uint4*)(sm + 2 * GRUW_B + r * (LDW * 2) + c * 16) =
                *(const uint4*)(hsh + (size_t)(mb * 32 + r) * DD + c * 8);
            *(uint4*)(sm + 2 * GRUW_B + GRUH_B + r * (LDW * 2) + c * 16) =
                *(const uint4*)(hsl + (size_t)(mb * 32 + r) * DD + c * 8);
        }
        __syncthreads();

        float acc0[4] = {0, 0, 0, 0}, acc1[4] = {0, 0, 0, 0};
        #pragma unroll 4
        for (int kc = 0; kc < 32; kc++) {
            uint32_t ah[4], al[4], bh[4], bl[4];
            ldsm_x4(ah, hb_h + kc * 32);
            ldsm_x4(al, hb_l + kc * 32);
            ldsm_x4(bh, wb_h + kc * 32);
            ldsm_x4(bl, wb_l + kc * 32);
            mma16816(acc0, ah, &bh[0]);
            mma16816(acc0, ah, &bl[0]);
            mma16816(acc0, al, &bh[0]);
            mma16816(acc1, ah, &bh[2]);
            mma16816(acc1, ah, &bl[2]);
            mma16816(acc1, al, &bh[2]);
        }

        // write G slice (fp32)
        {
            int gr0 = mb * 32 + warp_m * 16 + (lane >> 2);
            int gc  = nb * 64 + warp_n * 16 + (lane & 3) * 2;
            *(float2*)(G + (size_t)gr0 * D3 + gc)           = make_float2(acc0[0], acc0[1]);
            *(float2*)(G + (size_t)gr0 * D3 + gc + 8)       = make_float2(acc1[0], acc1[1]);
            *(float2*)(G + (size_t)(gr0 + 8) * D3 + gc)     = make_float2(acc0[2], acc0[3]);
            *(float2*)(G + (size_t)(gr0 + 8) * D3 + gc + 8) = make_float2(acc1[2], acc1[3]);
        }
        bar4(mb);

        // distributed pointwise: blocks nb < 16 handle j-chunk [nb*32, nb*32+32)
        if (nb < 16) {
            for (int idx = tid; idx < 1024; idx += 256) {
                int m_loc = idx >> 5, j_loc = idx & 31;
                int b = mb * 32 + m_loc;
                int j = nb * 32 + j_loc;
                float gr = G[(size_t)b * D3 + j];
                float gz = G[(size_t)b * D3 + DD + j];
                float gn = G[(size_t)b * D3 + 2 * DD + j];
                size_t xb = ((size_t)b * NS + t) * D3 + j;
                float xr = xp[xb], xz = xp[xb + DD], xn = xp[xb + 2 * DD];
                float r = sigmoid_fast(xr + gr + bhh[j]);
                float z = sigmoid_fast(xz + gz + bhh[DD + j]);
                float n = tanh_fast(xn + r * (gn + bhh[2 * DD + j]));
                float hp = hstate[(size_t)b * DD + j];
                float h2 = (1.0f - z) * n + z * hp;
                hstate[(size_t)b * DD + j] = h2;
                __nv_bfloat16 hb16 = __float2bfloat16_rn(h2);
                __nv_bfloat16 lb16 = __float2bfloat16_rn(h2 - __bfloat162float(hb16));
                hsh[(size_t)b * DD + j] = hb16;
                hsl[(size_t)b * DD + j] = lb16;
                size_t yi = ((size_t)b * NS + t) * DD + j;
                yh[yi] = hb16;
                yl[yi] = lb16;
                if (nb == 0 && j_loc == 0) maskp[(size_t)b * NS + t] = (h2 != 0.0f) ? 1.0f : 0.0f;
            }
        }
        bar4(mb);
    }
}

extern "C" void kernel_launch(void* const* d_in, const int* in_sizes, int n_in,
                              void* d_out, int out_size) {
    const int*   seqs  = (const int*)d_in[0];
    const float* enc   = (const float*)d_in[2];
    const float* h0    = (const float*)d_in[3];
    const float* emb   = (const float*)d_in[4];
    const float* w_ih  = (const float*)d_in[5];
    const float* w_hh  = (const float*)d_in[6];
    const float* b_ih  = (const float*)d_in[7];
    const float* b_hh  = (const float*)d_in[8];
    const float* attnw = (const float*)d_in[9];
    const float* attnb = (const float*)d_in[10];
    const float* outw  = (const float*)d_in[11];
    const float* outb  = (const float*)d_in[12];
    float* out = (float*)d_out;

    float *xp, *G, *hstate, *mask;
    __nv_bfloat16 *hsh, *hsl, *Ah, *Al, *Ph, *Pl, *Ch, *Cl, *Dh, *Dl;
    __nv_bfloat16 *ench, *encl, *encTh, *encTl, *wihh, *wihl, *whhh, *whhl, *awh, *awl, *owh, *owl;
    cudaGetSymbolAddress((void**)&xp,     g_xp);
    cudaGetSymbolAddress((void**)&G,      g_G);
    cudaGetSymbolAddress((void**)&hstate, g_h);
    cudaGetSymbolAddress((void**)&mask,   g_mask);
    cudaGetSymbolAddress((void**)&hsh, g_hsh);     cudaGetSymbolAddress((void**)&hsl, g_hsl);
    cudaGetSymbolAddress((void**)&Ah, g_Ah);   cudaGetSymbolAddress((void**)&Al, g_Al);
    cudaGetSymbolAddress((void**)&Ph, g_Ph);   cudaGetSymbolAddress((void**)&Pl, g_Pl);
    cudaGetSymbolAddress((void**)&Ch, g_Ch);   cudaGetSymbolAddress((void**)&Cl, g_Cl);
    cudaGetSymbolAddress((void**)&Dh, g_Dh);   cudaGetSymbolAddress((void**)&Dl, g_Dl);
    cudaGetSymbolAddress((void**)&ench, g_ench);   cudaGetSymbolAddress((void**)&encl, g_encl);
    cudaGetSymbolAddress((void**)&encTh, g_encTh); cudaGetSymbolAddress((void**)&encTl, g_encTl);
    cudaGetSymbolAddress((void**)&wihh, g_wihh);   cudaGetSymbolAddress((void**)&wihl, g_wihl);
    cudaGetSymbolAddress((void**)&whhh, g_whhh);   cudaGetSymbolAddress((void**)&whhl, g_whhl);
    cudaGetSymbolAddress((void**)&awh, g_awh);     cudaGetSymbolAddress((void**)&awl, g_awl);
    cudaGetSymbolAddress((void**)&owh, g_owh);     cudaGetSymbolAddress((void**)&owl, g_owl);

    static int attr_set = 0;
    if (!attr_set) {
        cudaFuncSetAttribute(gru_mma, cudaFuncAttributeMaxDynamicSharedMemorySize, GRU2_SMEM);
        cudaFuncSetAttribute(gemm_mma, cudaFuncAttributeMaxDynamicSharedMemorySize, GM_SMEM);
        attr_set = 1;
    }

    const size_t OUT_H    = (size_t)MALL * NV;
    const size_t OUT_ATTN = OUT_H + (size_t)NL * NB * DD;
    float* attnP = out + OUT_ATTN;
    const float SC = 0.044194173824159216f;

    convert_all<<<(S4 + 255) / 256, 256>>>(
        w_ih, w_hh, attnw, outw, enc,
        wihh, wihl, whhh, whhl, awh, awl, owh, owl, ench, encl);
    transpose_split_kernel<<<dim3(16, 16, 128), dim3(32, 8)>>>(enc, encTh, encTl);
    embed_split_kernel<<<(MALL * (DD / 4)) / 256, 256>>>(seqs, emb, Ah, Al);

    for (int l = 0; l < NL; l++) {
        gemm_mma<<<dim3(12, 512, 1), 256, GM_SMEM>>>(
            Ah, Al, nullptr, nullptr, DD, DD, DD,
            wihh + (size_t)l * D3 * DD, wihl + (size_t)l * D3 * DD, D3,
            xp, nullptr, nullptr, D3, 0, 0, 0, 1.0f, b_ih + (size_t)l * D3, nullptr, 0);
        h_init_kernel<<<(NB * DD / 4 + 255) / 256, 256>>>(
            h0 + (size_t)l * NB * DD, hstate, hsh, hsl);
        gru_mma<<<96, 256, GRU2_SMEM>>>(
            whhh + (size_t)l * D3 * DD, whhl + (size_t)l * D3 * DD,
            b_hh + (size_t)l * D3, xp, G, hstate, hsh, hsl, Ah, Al, mask);
        copy4_kernel<<<64, 256>>>(out + OUT_H + (size_t)l * NB * DD, hstate, NB * DD / 4);
    }

    gemm_mma<<<dim3(4, 4, 128), 256, GM_SMEM>>>(
        Ah, Al, nullptr, nullptr, DD, DD, DD,
        ench, encl, NSE,
        attnP, nullptr, nullptr, NSE, (size_t)NS * DD, (size_t)NSE * DD, (size_t)NS * NSE,
        SC, nullptr, nullptr, 0);
    softmax_kernel<<<MALL, 256>>>(attnP, Ph, Pl);

    gemm_mma<<<dim3(4, 4, 128), 256, GM_SMEM>>>(
        Ph, Pl, nullptr, nullptr, NSE, NSE, NSE,
        encTh, encTl, DD,
        nullptr, Ch, Cl, DD, (size_t)NS * NSE, (size_t)DD * NSE, (size_t)NS * DD,
        1.0f, nullptr, nullptr, 4);

    gemm_mma<<<dim3(4, 512, 1), 256, GM_SMEM>>>(
        Ah, Al, Ch, Cl, DD, DD, 2 * DD,
        awh, awl, DD,
        nullptr, Dh, Dl, DD, 0, 0, 0, 1.0f, attnb, mask, 5);

    gemm_mma<<<dim3(1, 512, 1), 256, GM_SMEM>>>(
        Dh, Dl, nullptr, nullptr, DD, DD, DD,
        owh, owl, NV,
        out, nullptr, nullptr, NV, 0, 0, 0, 1.0f, outb, mask, 2);
}

// round 13
// speedup vs baseline: 1.3238x; 1.3238x over previous
#include <cuda_runtime.h>
#include <cuda_bf16.h>
#include <math.h>
#include <stdint.h>

#define NL 3
#define DD 512
#define NV 100
#define NB 128
#define NS 512
#define NSE 512
#define MALL (NB*NS)
#define D3 (3*DD)

// ---------------- scratch ----------------
__device__ float g_xp[(size_t)MALL * D3];
__device__ float g_h[NB * DD];
__device__ float g_mask[MALL];
__device__ unsigned g_cnt4[4];
__device__ volatile unsigned g_gen4[4];
__device__ __nv_bfloat16 g_hsh[NB * DD];
__device__ __nv_bfloat16 g_hsl[NB * DD];
__device__ __nv_bfloat16 g_Ah[(size_t)MALL * DD];
__device__ __nv_bfloat16 g_Al[(size_t)MALL * DD];
__device__ __nv_bfloat16 g_Ph[(size_t)MALL * NSE];
__device__ __nv_bfloat16 g_Pl[(size_t)MALL * NSE];
__device__ __nv_bfloat16 g_Ch[(size_t)MALL * DD];
__device__ __nv_bfloat16 g_Cl[(size_t)MALL * DD];
__device__ __nv_bfloat16 g_Dh[(size_t)MALL * DD];
__device__ __nv_bfloat16 g_Dl[(size_t)MALL * DD];
__device__ __nv_bfloat16 g_ench[(size_t)NB * NSE * DD];
__device__ __nv_bfloat16 g_encl[(size_t)NB * NSE * DD];
__device__ __nv_bfloat16 g_encTh[(size_t)NB * DD * NSE];
__device__ __nv_bfloat16 g_encTl[(size_t)NB * DD * NSE];
__device__ __nv_bfloat16 g_wihh[(size_t)NL * D3 * DD];
__device__ __nv_bfloat16 g_wihl[(size_t)NL * D3 * DD];
__device__ __nv_bfloat16 g_whhh[(size_t)NL * D3 * DD];
__device__ __nv_bfloat16 g_whhl[(size_t)NL * D3 * DD];
__device__ __nv_bfloat16 g_awh[(size_t)DD * 2 * DD];
__device__ __nv_bfloat16 g_awl[(size_t)DD * 2 * DD];
__device__ __nv_bfloat16 g_owh[128 * DD];
__device__ __nv_bfloat16 g_owl[128 * DD];

extern __shared__ float smf[];

// ---------------- helpers ----------------
__device__ __forceinline__ float tanh_fast(float x) {
    float y;
    asm("tanh.approx.f32 %0, %1;" : "=f"(y) : "f"(x));
    return y;
}
__device__ __forceinline__ float sigmoid_fast(float x) { return 1.0f / (1.0f + __expf(-x)); }
__device__ __forceinline__ uint32_t smem_u32(const void* p) {
    uint32_t a;
    asm("{ .reg .u64 t; cvta.to.shared.u64 t, %1; cvt.u32.u64 %0, t; }" : "=r"(a) : "l"(p));
    return a;
}
__device__ __forceinline__ unsigned bfu(__nv_bfloat16 b) {
    unsigned short s = __bfloat16_as_ushort(b);
    return (unsigned)s;
}
__device__ __forceinline__ void split_store(float4 v, __nv_bfloat16* h, __nv_bfloat16* l, size_t i4) {
    __nv_bfloat16 h0 = __float2bfloat16_rn(v.x), h1 = __float2bfloat16_rn(v.y);
    __nv_bfloat16 h2 = __float2bfloat16_rn(v.z), h3 = __float2bfloat16_rn(v.w);
    uint2 hv, lv;
    hv.x = bfu(h0) | (bfu(h1) << 16); hv.y = bfu(h2) | (bfu(h3) << 16);
    lv.x = bfu(__float2bfloat16_rn(v.x - __bfloat162float(h0))) |
           (bfu(__float2bfloat16_rn(v.y - __bfloat162float(h1))) << 16);
    lv.y = bfu(__float2bfloat16_rn(v.z - __bfloat162float(h2))) |
           (bfu(__float2bfloat16_rn(v.w - __bfloat162float(h3))) << 16);
    ((uint2*)h)[i4] = hv; ((uint2*)l)[i4] = lv;
}

// ---------------- mma.sync primitives ----------------
__device__ __forceinline__ void mma16816(float* d, const uint32_t* a, const uint32_t* b) {
    asm volatile(
        "mma.sync.aligned.m16n8k16.row.col.f32.bf16.bf16.f32 "
        "{%0,%1,%2,%3}, {%4,%5,%6,%7}, {%8,%9}, {%0,%1,%2,%3};"
        : "+f"(d[0]), "+f"(d[1]), "+f"(d[2]), "+f"(d[3])
        : "r"(a[0]), "r"(a[1]), "r"(a[2]), "r"(a[3]), "r"(b[0]), "r"(b[1]));
}
__device__ __forceinline__ void ldsm_x4(uint32_t* r, uint32_t addr) {
    asm volatile("ldmatrix.sync.aligned.m8n8.x4.shared.b16 {%0,%1,%2,%3}, [%4];"
        : "=r"(r[0]), "=r"(r[1]), "=r"(r[2]), "=r"(r[3]) : "r"(addr));
}
__device__ __forceinline__ void cpasync16(uint32_t dst, const void* src, int sz) {
    asm volatile("cp.async.ca.shared.global [%0], [%1], 16, %2;" :: "r"(dst), "l"(src), "r"(sz) : "memory");
}
#define CP_COMMIT() asm volatile("cp.async.commit_group;" ::: "memory")
#define CP_WAIT1()  asm volatile("cp.async.wait_group 1;" ::: "memory")
#define CP_WAIT0()  asm volatile("cp.async.wait_group 0;" ::: "memory")

// ---------------- merged conversions ----------------
#define S0 589824u
#define S1 (S0 + 589824u)
#define S2 (S1 + 131072u)
#define S3 (S2 + 8388608u)
#define S4 (S3 + 16384u)
__global__ void convert_all(
    const float* __restrict__ w_ih, const float* __restrict__ w_hh,
    const float* __restrict__ attnw, const float* __restrict__ outw,
    const float* __restrict__ enc,
    __nv_bfloat16* __restrict__ wihh, __nv_bfloat16* __restrict__ wihl,
    __nv_bfloat16* __restrict__ whhh, __nv_bfloat16* __restrict__ whhl,
    __nv_bfloat16* __restrict__ awh,  __nv_bfloat16* __restrict__ awl,
    __nv_bfloat16* __restrict__ owh,  __nv_bfloat16* __restrict__ owl,
    __nv_bfloat16* __restrict__ ench, __nv_bfloat16* __restrict__ encl)
{
    unsigned i = blockIdx.x * 256 + threadIdx.x;
    if (i >= S4) return;
    if (i < S0) {
        split_store(((const float4*)w_ih)[i], wihh, wihl, i);
    } else if (i < S1) {
        unsigned j = i - S0;
        split_store(((const float4*)w_hh)[j], whhh, whhl, j);
    } else if (i < S2) {
        unsigned j = i - S1;
        split_store(((const float4*)attnw)[j], awh, awl, j);
    } else if (i < S3) {
        unsigned j = i - S2;
        split_store(((const float4*)enc)[j], ench, encl, j);
    } else {
        unsigned j = i - S3;
        unsigned r = j >> 7;
        float4 v = make_float4(0.f, 0.f, 0.f, 0.f);
        if (r < NV) v = ((const float4*)outw)[j];
        split_store(v, owh, owl, j);
    }
}

__global__ void transpose_split_kernel(const float* __restrict__ enc,
                                       __nv_bfloat16* __restrict__ th, __nv_bfloat16* __restrict__ tl) {
    __shared__ float tile[32][33];
    int b = blockIdx.z;
    int d0 = blockIdx.x * 32, s0 = blockIdx.y * 32;
    int x = threadIdx.x, y = threadIdx.y;
    #pragma unroll
    for (int i = 0; i < 32; i += 8)
        tile[y + i][x] = enc[((size_t)b * NSE + s0 + y + i) * DD + d0 + x];
    __syncthreads();
    #pragma unroll
    for (int i = 0; i < 32; i += 8) {
        float v = tile[x][y + i];
        __nv_bfloat16 hb = __float2bfloat16_rn(v);
        size_t o = ((size_t)b * DD + d0 + y + i) * NSE + s0 + x;
        th[o] = hb;
        tl[o] = __float2bfloat16_rn(v - __bfloat162float(hb));
    }
}

__global__ void embed_split_kernel(const int* __restrict__ seqs, const float* __restrict__ emb,
                                   __nv_bfloat16* __restrict__ h, __nv_bfloat16* __restrict__ l) {
    size_t i = (size_t)blockIdx.x * blockDim.x + threadIdx.x;
    size_t row = i >> 7;
    int c = (int)(i & 127);
    int tok = seqs[row];
    split_store(((const float4*)(emb + (size_t)tok * DD))[c], h, l, i);
}
__global__ void copy4_kernel(float* __restrict__ dst, const float* __restrict__ src, int n4) {
    int i = blockIdx.x * blockDim.x + threadIdx.x;
    if (i < n4) ((float4*)dst)[i] = ((const float4*)src)[i];
}
__global__ void h_init_kernel(const float* __restrict__ h0, float* __restrict__ hstate,
                              __nv_bfloat16* __restrict__ hh, __nv_bfloat16* __restrict__ hl) {
    int i = blockIdx.x * 256 + threadIdx.x;
    if (i >= NB * DD / 4) return;
    float4 v = ((const float4*)h0)[i];
    ((float4*)hstate)[i] = v;
    split_store(v, hh, hl, i);
}
__global__ void softmax_kernel(float* __restrict__ P, __nv_bfloat16* __restrict__ ph,
                               __nv_bfloat16* __restrict__ pl) {
    __shared__ float red[256];
    size_t row = blockIdx.x;
    float* p = P + row * NSE;
    int tid = threadIdx.x;
    float v0 = p[tid], v1 = p[tid + 256];
    red[tid] = fmaxf(v0, v1); __syncthreads();
    #pragma unroll
    for (int s = 128; s > 0; s >>= 1) { if (tid < s) red[tid] = fmaxf(red[tid], red[tid + s]); __syncthreads(); }
    float mx = red[0]; __syncthreads();
    float e0 = __expf(v0 - mx), e1 = __expf(v1 - mx);
    red[tid] = e0 + e1; __syncthreads();
    #pragma unroll
    for (int s = 128; s > 0; s >>= 1) { if (tid < s) red[tid] += red[tid + s]; __syncthreads(); }
    float inv = 1.0f / red[0];
    float o0 = e0 * inv, o1 = e1 * inv;
    p[tid] = o0; p[tid + 256] = o1;
    __nv_bfloat16 b0 = __float2bfloat16_rn(o0), b1 = __float2bfloat16_rn(o1);
    ph[row * NSE + tid] = b0;
    ph[row * NSE + tid + 256] = b1;
    pl[row * NSE + tid] = __float2bfloat16_rn(o0 - __bfloat162float(b0));
    pl[row * NSE + tid + 256] = __float2bfloat16_rn(o1 - __bfloat162float(b1));
}

// ---------------- mma.sync split-bf16 NT GEMM, 2-stage, 2 blocks/SM ----------------
#define LDT 40
#define TILE_B (128 * LDT * 2)
#define STAGE_B (4 * TILE_B)
#define GM_SMEM (2 * STAGE_B)
__global__ void __launch_bounds__(256, 2) gemm_mma(
    const __nv_bfloat16* __restrict__ A0h, const __nv_bfloat16* __restrict__ A0l,
    const __nv_bfloat16* __restrict__ A1h, const __nv_bfloat16* __restrict__ A1l,
    int K0, int K1, int K,
    const __nv_bfloat16* __restrict__ Wh, const __nv_bfloat16* __restrict__ Wl, int nvalid,
    float* __restrict__ C, __nv_bfloat16* __restrict__ Obh, __nv_bfloat16* __restrict__ Obl, int ldc,
    size_t sA, size_t sW, size_t sC,
    float scale, const float* __restrict__ bias, const float* __restrict__ mask, int epi)
{
    uint32_t smb = smem_u32(smf);
    int tid = threadIdx.x, lane = tid & 31, wid = tid >> 5;
    int wm = wid >> 2, wn = wid & 3;
    int bz = blockIdx.z;
    int nBase = blockIdx.x * 128, mBase = blockIdx.y * 128;
    const __nv_bfloat16* a0h = A0h + (size_t)bz * sA;
    const __nv_bfloat16* a0l = A0l + (size_t)bz * sA;
    const __nv_bfloat16* wh  = Wh  + (size_t)bz * sW;
    const __nv_bfloat16* wl  = Wl  + (size_t)bz * sW;
    float* Cb = C + (size_t)bz * sC;
    __nv_bfloat16* obh = Obh + (size_t)bz * sC;
    __nv_bfloat16* obl = Obl + (size_t)bz * sC;

    float acc[4][4][4];
    #pragma unroll
    for (int i = 0; i < 4; i++)
        #pragma unroll
        for (int j = 0; j < 4; j++)
            #pragma unroll
            for (int q = 0; q < 4; q++) acc[i][j][q] = 0.0f;

    auto load_chunk = [&](int buf, int c) {
        int kOff = c * 32;
        const __nv_bfloat16 *ah, *al;
        int lda, ka;
        if (kOff < K0) { ah = a0h; al = a0l; lda = K0; ka = kOff; }
        else           { ah = A1h; al = A1l; lda = K1; ka = kOff - K0; }
        uint32_t sb = smb + buf * STAGE_B;
        #pragma unroll
        for (int p = 0; p < 8; p++) {
            int idx = p * 256 + tid;
            int tile = idx >> 9, rem = idx & 511;
            int r = rem >> 2, c16 = rem & 3;
            uint32_t dst = sb + tile * TILE_B + r * (LDT * 2) + c16 * 16;
            if (tile == 0)      cpasync16(dst, ah + (size_t)(mBase + r) * lda + ka + c16 * 8, 16);
            else if (tile == 1) cpasync16(dst, al + (size_t)(mBase + r) * lda + ka + c16 * 8, 16);
            else if (tile == 2) cpasync16(dst, wh + (size_t)(nBase + r) * K + kOff + c16 * 8, (nBase + r < nvalid) ? 16 : 0);
            else                cpasync16(dst, wl + (size_t)(nBase + r) * K + kOff + c16 * 8, (nBase + r < nvalid) ? 16 : 0);
        }
    };

    int aRow = lane & 15, aK = (lane >> 4) * 8;
    int bRow = (lane & 7) + ((lane >> 4) & 1) * 8, bK = ((lane >> 3) & 1) * 8;

    int nk = K / 32;
    load_chunk(0, 0);
    CP_COMMIT();
    for (int c = 0; c < nk; c++) {
        if (c + 1 < nk) { load_chunk((c + 1) & 1, c + 1); CP_COMMIT(); CP_WAIT1(); }
        else            { CP_WAIT0(); }
        __syncthreads();
        uint32_t sb = smb + (c & 1) * STAGE_B;
        #pragma unroll
        for (int ks = 0; ks < 2; ks++) {
            uint32_t ahf[4][4], alf[4][4];
            #pragma unroll
            for (int mf = 0; mf < 4; mf++) {
                uint32_t ra = sb + ((wm * 64 + mf * 16 + aRow) * LDT + ks * 16 + aK) * 2;
                ldsm_x4(ahf[mf], ra);
                ldsm_x4(alf[mf], ra + TILE_B);
            }
            #pragma unroll
            for (int np = 0; np < 2; np++) {
                uint32_t rb = sb + 2 * TILE_B + ((wn * 32 + np * 16 + bRow) * LDT + ks * 16 + bK) * 2;
                uint32_t bh[4], bl[4];
                ldsm_x4(bh, rb);
                ldsm_x4(bl, rb + TILE_B);
                #pragma unroll
                for (int mf = 0; mf < 4; mf++) {
                    mma16816(acc[mf][np * 2 + 0], ahf[mf], &bh[0]);
                    mma16816(acc[mf][np * 2 + 0], ahf[mf], &bl[0]);
                    mma16816(acc[mf][np * 2 + 0], alf[mf], &bh[0]);
                    mma16816(acc[mf][np * 2 + 1], ahf[mf], &bh[2]);
                    mma16816(acc[mf][np * 2 + 1], ahf[mf], &bl[2]);
                    mma16816(acc[mf][np * 2 + 1], alf[mf], &bh[2]);
                }
            }
        }
        __syncthreads();
    }

    int rOff = lane >> 2, cOff = (lane & 3) * 2;
    #pragma unroll
    for (int mf = 0; mf < 4; mf++) {
        int mrow0 = mBase + wm * 64 + mf * 16 + rOff;
        int mrow1 = mrow0 + 8;
        float mk0 = 1.0f, mk1 = 1.0f;
        if (epi == 2 || epi == 5) {
            mk0 = mask[(size_t)bz * (sC / ldc) + mrow0];
            mk1 = mask[(size_t)bz * (sC / ldc) + mrow1];
        }
        #pragma unroll
        for (int nf = 0; nf < 4; nf++) {
            int col = nBase + wn * 32 + nf * 8 + cOff;
            if (col >= nvalid) continue;
            float v0 = acc[mf][nf][0] * scale, v1 = acc[mf][nf][1] * scale;
            float v2 = acc[mf][nf][2] * scale, v3 = acc[mf][nf][3] * scale;
            if (bias) {
                float b0 = bias[col], b1 = bias[col + 1];
                v0 += b0; v1 += b1; v2 += b0; v3 += b1;
            }
            if (epi == 0) {
                *(float2*)(Cb + (size_t)mrow0 * ldc + col) = make_float2(v0, v1);
                *(float2*)(Cb + (size_t)mrow1 * ldc + col) = make_float2(v2, v3);
            } else if (epi == 2) {
                v0 *= mk0; v1 *= mk0; v2 *= mk1; v3 *= mk1;
                *(float2*)(Cb + (size_t)mrow0 * ldc + col) = make_float2(v0, v1);
                *(float2*)(Cb + (size_t)mrow1 * ldc + col) = make_float2(v2, v3);
            } else {
                if (epi == 5) {
                    v0 = tanh_fast(v0) * mk0; v1 = tanh_fast(v1) * mk0;
                    v2 = tanh_fast(v2) * mk1; v3 = tanh_fast(v3) * mk1;
                }
                __nv_bfloat16 h0 = __float2bfloat16_rn(v0), h1 = __float2bfloat16_rn(v1);
                __nv_bfloat16 h2 = __float2bfloat16_rn(v2), h3 = __float2bfloat16_rn(v3);
                uint32_t hp0 = bfu(h0) | (bfu(h1) << 16);
                uint32_t hp1 = bfu(h2) | (bfu(h3) << 16);
                uint32_t lp0 = bfu(__float2bfloat16_rn(v0 - __bfloat162float(h0))) |
                               (bfu(__float2bfloat16_rn(v1 - __bfloat162float(h1))) << 16);
                uint32_t lp1 = bfu(__float2bfloat16_rn(v2 - __bfloat162float(h2))) |
                               (bfu(__float2bfloat16_rn(v3 - __bfloat162float(h3))) << 16);
                *(uint32_t*)(obh + (size_t)mrow0 * ldc + col) = hp0;
                *(uint32_t*)(obh + (size_t)mrow1 * ldc + col) = hp1;
                *(uint32_t*)(obl + (size_t)mrow0 * ldc + col) = lp0;
                *(uint32_t*)(obl + (size_t)mrow1 * ldc + col) = lp1;
            }
        }
    }
}

// ---------------- per-m-group barrier (32 blocks per group) ----------------
__device__ __forceinline__ void bar4(int grp) {
    __syncthreads();
    if (threadIdx.x == 0) {
        __threadfence();
        unsigned gen = g_gen4[grp];
        unsigned old = atomicAdd(&g_cnt4[grp], 1);
        if (old == 31u) {
            atomicExch(&g_cnt4[grp], 0u);
            __threadfence();
            g_gen4[grp] = gen + 1u;
        } else {
            while (g_gen4[grp] == gen) { }
        }
        __threadfence();
    }
    __syncthreads();
}

// ---------------- persistent tensor-core GRU, gate-interleaved, 1 barrier/step ----------------
// 128 blocks = 4 m-groups (32 batch rows) x 32 j-tiles (16 j's; 48 W rows = 3 gates x 16 j).
// 192 threads = 6 warps (warp_m in 0..1, warp_g in 0..2). Pointwise is block-local via smem gbuf.
#define LDW 520
#define GRUW_B (48 * LDW * 2)        // 49920 per W array
#define GRUH_B (32 * LDW * 2)        // 33280 per h array
#define GBUF_OFF (2 * GRUW_B + 2 * GRUH_B)    // 166400
#define GRU2_SMEM (GBUF_OFF + 3 * 32 * 16 * 4) // +6144 = 172544
__global__ void __launch_bounds__(192, 1) gru_mma(
    const __nv_bfloat16* __restrict__ Wh, const __nv_bfloat16* __restrict__ Wl,
    const float* __restrict__ bhh, const float* __restrict__ xp,
    float* __restrict__ hstate,
    __nv_bfloat16* __restrict__ hsh, __nv_bfloat16* __restrict__ hsl,
    __nv_bfloat16* __restrict__ yh, __nv_bfloat16* __restrict__ yl,
    float* __restrict__ maskp)
{
    char* sm = (char*)smf;
    uint32_t smb = smem_u32(sm);
    float* gbuf = (float*)(sm + GBUF_OFF);    // [3][32][16]
    int tid = threadIdx.x, lane = tid & 31, w = tid >> 5;
    int mb = blockIdx.x >> 5, jb = blockIdx.x & 31;
    int warp_m = w & 1, warp_g = w >> 1;      // 2 x 3
    int jBase = jb * 16;

    // stage W slice: 48 rows = gate g, local jj -> global row g*512 + jBase + jj
    for (int idx = tid; idx < 48 * 64; idx += 192) {
        int r = idx >> 6, c = idx & 63;
        int g = r >> 4, jj = r & 15;
        size_t grow = (size_t)(g * DD + jBase + jj);
        *(uint4*)(sm + r * (LDW * 2) + c * 16) = *(const uint4*)(Wh + grow * DD + c * 8);
        *(uint4*)(sm + GRUW_B + r * (LDW * 2) + c * 16) = *(const uint4*)(Wl + grow * DD + c * 8);
    }

    int aRow = lane & 15, aK = (lane >> 4) * 8;
    int bRow = (lane & 7) + ((lane >> 4) & 1) * 8, bK = ((lane >> 3) & 1) * 8;
    uint32_t wb_h = smb + ((warp_g * 16 + bRow) * LDW + bK) * 2;
    uint32_t wb_l = wb_h + GRUW_B;
    uint32_t hb_h = smb + 2 * GRUW_B + ((warp_m * 16 + aRow) * LDW + aK) * 2;
    uint32_t hb_l = hb_h + GRUH_B;

    for (int t = 0; t < NS; t++) {
        // stage h tile (32 rows x 512, hi+lo)
        for (int idx = tid; idx < 32 * 64; idx += 192) {
            int r = idx >> 6, c = idx & 63;
            *(uint4*)(sm + 2 * GRUW_B + r * (LDW * 2) + c * 16) =
                *(const uint4*)(hsh + (size_t)(mb * 32 + r) * DD + c * 8);
            *(uint4*)(sm + 2 * GRUW_B + GRUH_B + r * (LDW * 2) + c * 16) =
                *(const uint4*)(hsl + (size_t)(mb * 32 + r) * DD + c * 8);
        }
        __syncthreads();

        float acc0[4] = {0, 0, 0, 0}, acc1[4] = {0, 0, 0, 0};
        #pragma unroll 4
        for (int kc = 0; kc < 32; kc++) {
            uint32_t ah[4], al[4], bh[4], bl[4];
            ldsm_x4(ah, hb_h + kc * 32);
            ldsm_x4(al, hb_l + kc * 32);
            ldsm_x4(bh, wb_h + kc * 32);
            ldsm_x4(bl, wb_l + kc * 32);
            mma16816(acc0, ah, &bh[0]);
            mma16816(acc0, ah, &bl[0]);
            mma16816(acc0, al, &bh[0]);
            mma16816(acc1, ah, &bh[2]);
            mma16816(acc1, ah, &bl[2]);
            mma16816(acc1, al, &bh[2]);
        }

        // write gate slice into gbuf[warp_g][m 32][j 16]
        {
            int m0 = warp_m * 16 + (lane >> 2);
            int jc = (lane & 3) * 2;
            float* gb = gbuf + (warp_g * 32 + m0) * 16;
            gb[jc] = acc0[0];     gb[jc + 1] = acc0[1];
            gb[jc + 8] = acc1[0]; gb[jc + 9] = acc1[1];
            gb += 8 * 16;
            gb[jc] = acc0[2];     gb[jc + 1] = acc0[3];
            gb[jc + 8] = acc1[2]; gb[jc + 9] = acc1[3];
        }
        __syncthreads();

        // local pointwise: 32 m x 16 j = 512 elems over 192 threads
        for (int idx = tid; idx < 512; idx += 192) {
            int m_loc = idx >> 4, j_loc = idx & 15;
            int b = mb * 32 + m_loc;
            int j = jBase + j_loc;
            float gr = gbuf[(0 * 32 + m_loc) * 16 + j_loc];
            float gz = gbuf[(1 * 32 + m_loc) * 16 + j_loc];
            float gn = gbuf[(2 * 32 + m_loc) * 16 + j_loc];
            size_t xb = ((size_t)b * NS + t) * D3 + j;
            float xr = xp[xb], xz = xp[xb + DD], xn = xp[xb + 2 * DD];
            float r = sigmoid_fast(xr + gr + bhh[j]);
            float z = sigmoid_fast(xz + gz + bhh[DD + j]);
            float n = tanh_fast(xn + r * (gn + bhh[2 * DD + j]));
            float hp = hstate[(size_t)b * DD + j];
            float h2 = (1.0f - z) * n + z * hp;
            hstate[(size_t)b * DD + j] = h2;
            __nv_bfloat16 hb16 = __float2bfloat16_rn(h2);
            __nv_bfloat16 lb16 = __float2bfloat16_rn(h2 - __bfloat162float(hb16));
            hsh[(size_t)b * DD + j] = hb16;
            hsl[(size_t)b * DD + j] = lb16;
            size_t yi = ((size_t)b * NS + t) * DD + j;
            yh[yi] = hb16;
            yl[yi] = lb16;
            if (j == 0) maskp[(size_t)b * NS + t] = (h2 != 0.0f) ? 1.0f : 0.0f;
        }
        bar4(mb);
    }
}

extern "C" void kernel_launch(void* const* d_in, const int* in_sizes, int n_in,
                              void* d_out, int out_size) {
    const int*   seqs  = (const int*)d_in[0];
    const float* enc   = (const float*)d_in[2];
    const float* h0    = (const float*)d_in[3];
    const float* emb   = (const float*)d_in[4];
    const float* w_ih  = (const float*)d_in[5];
    const float* w_hh  = (const float*)d_in[6];
    const float* b_ih  = (const float*)d_in[7];
    const float* b_hh  = (const float*)d_in[8];
    const float* attnw = (const float*)d_in[9];
    const float* attnb = (const float*)d_in[10];
    const float* outw  = (const float*)d_in[11];
    const float* outb  = (const float*)d_in[12];
    float* out = (float*)d_out;

    float *xp, *hstate, *mask;
    __nv_bfloat16 *hsh, *hsl, *Ah, *Al, *Ph, *Pl, *Ch, *Cl, *Dh, *Dl;
    __nv_bfloat16 *ench, *encl, *encTh, *encTl, *wihh, *wihl, *whhh, *whhl, *awh, *awl, *owh, *owl;
    cudaGetSymbolAddress((void**)&xp,     g_xp);
    cudaGetSymbolAddress((void**)&hstate, g_h);
    cudaGetSymbolAddress((void**)&mask,   g_mask);
    cudaGetSymbolAddress((void**)&hsh, g_hsh);     cudaGetSymbolAddress((void**)&hsl, g_hsl);
    cudaGetSymbolAddress((void**)&Ah, g_Ah);   cudaGetSymbolAddress((void**)&Al, g_Al);
    cudaGetSymbolAddress((void**)&Ph, g_Ph);   cudaGetSymbolAddress((void**)&Pl, g_Pl);
    cudaGetSymbolAddress((void**)&Ch, g_Ch);   cudaGetSymbolAddress((void**)&Cl, g_Cl);
    cudaGetSymbolAddress((void**)&Dh, g_Dh);   cudaGetSymbolAddress((void**)&Dl, g_Dl);
    cudaGetSymbolAddress((void**)&ench, g_ench);   cudaGetSymbolAddress((void**)&encl, g_encl);
    cudaGetSymbolAddress((void**)&encTh, g_encTh); cudaGetSymbolAddress((void**)&encTl, g_encTl);
    cudaGetSymbolAddress((void**)&wihh, g_wihh);   cudaGetSymbolAddress((void**)&wihl, g_wihl);
    cudaGetSymbolAddress((void**)&whhh, g_whhh);   cudaGetSymbolAddress((void**)&whhl, g_whhl);
    cudaGetSymbolAddress((void**)&awh, g_awh);     cudaGetSymbolAddress((void**)&awl, g_awl);
    cudaGetSymbolAddress((void**)&owh, g_owh);     cudaGetSymbolAddress((void**)&owl, g_owl);

    static int attr_set = 0;
    if (!attr_set) {
        cudaFuncSetAttribute(gru_mma, cudaFuncAttributeMaxDynamicSharedMemorySize, GRU2_SMEM);
        cudaFuncSetAttribute(gemm_mma, cudaFuncAttributeMaxDynamicSharedMemorySize, GM_SMEM);
        attr_set = 1;
    }

    const size_t OUT_H    = (size_t)MALL * NV;
    const size_t OUT_ATTN = OUT_H + (size_t)NL * NB * DD;
    float* attnP = out + OUT_ATTN;
    const float SC = 0.044194173824159216f;

    convert_all<<<(S4 + 255) / 256, 256>>>(
        w_ih, w_hh, attnw, outw, enc,
        wihh, wihl, whhh, whhl, awh, awl, owh, owl, ench, encl);
    transpose_split_kernel<<<dim3(16, 16, 128), dim3(32, 8)>>>(enc, encTh, encTl);
    embed_split_kernel<<<(MALL * (DD / 4)) / 256, 256>>>(seqs, emb, Ah, Al);

    for (int l = 0; l < NL; l++) {
        gemm_mma<<<dim3(12, 512, 1), 256, GM_SMEM>>>(
            Ah, Al, nullptr, nullptr, DD, DD, DD,
            wihh + (size_t)l * D3 * DD, wihl + (size_t)l * D3 * DD, D3,
            xp, nullptr, nullptr, D3, 0, 0, 0, 1.0f, b_ih + (size_t)l * D3, nullptr, 0);
        h_init_kernel<<<(NB * DD / 4 + 255) / 256, 256>>>(
            h0 + (size_t)l * NB * DD, hstate, hsh, hsl);
        gru_mma<<<128, 192, GRU2_SMEM>>>(
            whhh + (size_t)l * D3 * DD, whhl + (size_t)l * D3 * DD,
            b_hh + (size_t)l * D3, xp, hstate, hsh, hsl, Ah, Al, mask);
        copy4_kernel<<<64, 256>>>(out + OUT_H + (size_t)l * NB * DD, hstate, NB * DD / 4);
    }

    gemm_mma<<<dim3(4, 4, 128), 256, GM_SMEM>>>(
        Ah, Al, nullptr, nullptr, DD, DD, DD,
        ench, encl, NSE,
        attnP, nullptr, nullptr, NSE, (size_t)NS * DD, (size_t)NSE * DD, (size_t)NS * NSE,
        SC, nullptr, nullptr, 0);
    softmax_kernel<<<MALL, 256>>>(attnP, Ph, Pl);

    gemm_mma<<<dim3(4, 4, 128), 256, GM_SMEM>>>(
        Ph, Pl, nullptr, nullptr, NSE, NSE, NSE,
        encTh, encTl, DD,
        nullptr, Ch, Cl, DD, (size_t)NS * NSE, (size_t)DD * NSE, (size_t)NS * DD,
        1.0f, nullptr, nullptr, 4);

    gemm_mma<<<dim3(4, 512, 1), 256, GM_SMEM>>>(
        Ah, Al, Ch, Cl, DD, DD, 2 * DD,
        awh, awl, DD,
        nullptr, Dh, Dl, DD, 0, 0, 0, 1.0f, attnb, mask, 5);

    gemm_mma<<<dim3(1, 512, 1), 256, GM_SMEM>>>(
        Dh, Dl, nullptr, nullptr, DD, DD, DD,
        owh, owl, NV,
        out, nullptr, nullptr, NV, 0, 0, 0, 1.0f, outb, mask, 2);
}

// round 14
// speedup vs baseline: 1.5722x; 1.1877x over previous
#include <cuda_runtime.h>
#include <cuda_bf16.h>
#include <math.h>
#include <stdint.h>

#define NL 3
#define DD 512
#define NV 100
#define NB 128
#define NS 512
#define NSE 512
#define MALL (NB*NS)
#define D3 (3*DD)

// ---------------- scratch ----------------
__device__ float g_xp[(size_t)MALL * D3];
__device__ float g_h[NB * DD];
__device__ float g_mask[MALL];
__device__ unsigned g_cnt4[4];
__device__ volatile unsigned g_gen4[4];
__device__ __nv_bfloat16 g_hsh[2 * NB * DD];   // double-buffered h state (bf16 split)
__device__ __nv_bfloat16 g_hsl[2 * NB * DD];
__device__ __nv_bfloat16 g_Ah[(size_t)MALL * DD];
__device__ __nv_bfloat16 g_Al[(size_t)MALL * DD];
__device__ __nv_bfloat16 g_Ph[(size_t)MALL * NSE];
__device__ __nv_bfloat16 g_Pl[(size_t)MALL * NSE];
__device__ __nv_bfloat16 g_Ch[(size_t)MALL * DD];
__device__ __nv_bfloat16 g_Cl[(size_t)MALL * DD];
__device__ __nv_bfloat16 g_Dh[(size_t)MALL * DD];
__device__ __nv_bfloat16 g_Dl[(size_t)MALL * DD];
__device__ __nv_bfloat16 g_ench[(size_t)NB * NSE * DD];
__device__ __nv_bfloat16 g_encl[(size_t)NB * NSE * DD];
__device__ __nv_bfloat16 g_encTh[(size_t)NB * DD * NSE];
__device__ __nv_bfloat16 g_encTl[(size_t)NB * DD * NSE];
__device__ __nv_bfloat16 g_wihh[(size_t)NL * D3 * DD];
__device__ __nv_bfloat16 g_wihl[(size_t)NL * D3 * DD];
__device__ __nv_bfloat16 g_whhh[(size_t)NL * D3 * DD];
__device__ __nv_bfloat16 g_whhl[(size_t)NL * D3 * DD];
__device__ __nv_bfloat16 g_awh[(size_t)DD * 2 * DD];
__device__ __nv_bfloat16 g_awl[(size_t)DD * 2 * DD];
__device__ __nv_bfloat16 g_owh[128 * DD];
__device__ __nv_bfloat16 g_owl[128 * DD];

extern __shared__ float smf[];

// ---------------- helpers ----------------
__device__ __forceinline__ float tanh_fast(float x) {
    float y;
    asm("tanh.approx.f32 %0, %1;" : "=f"(y) : "f"(x));
    return y;
}
__device__ __forceinline__ float sigmoid_fast(float x) { return 1.0f / (1.0f + __expf(-x)); }
__device__ __forceinline__ uint32_t smem_u32(const void* p) {
    uint32_t a;
    asm("{ .reg .u64 t; cvta.to.shared.u64 t, %1; cvt.u32.u64 %0, t; }" : "=r"(a) : "l"(p));
    return a;
}
__device__ __forceinline__ unsigned bfu(__nv_bfloat16 b) {
    unsigned short s = __bfloat16_as_ushort(b);
    return (unsigned)s;
}
__device__ __forceinline__ void split_store(float4 v, __nv_bfloat16* h, __nv_bfloat16* l, size_t i4) {
    __nv_bfloat16 h0 = __float2bfloat16_rn(v.x), h1 = __float2bfloat16_rn(v.y);
    __nv_bfloat16 h2 = __float2bfloat16_rn(v.z), h3 = __float2bfloat16_rn(v.w);
    uint2 hv, lv;
    hv.x = bfu(h0) | (bfu(h1) << 16); hv.y = bfu(h2) | (bfu(h3) << 16);
    lv.x = bfu(__float2bfloat16_rn(v.x - __bfloat162float(h0))) |
           (bfu(__float2bfloat16_rn(v.y - __bfloat162float(h1))) << 16);
    lv.y = bfu(__float2bfloat16_rn(v.z - __bfloat162float(h2))) |
           (bfu(__float2bfloat16_rn(v.w - __bfloat162float(h3))) << 16);
    ((uint2*)h)[i4] = hv; ((uint2*)l)[i4] = lv;
}

// ---------------- mma.sync primitives ----------------
__device__ __forceinline__ void mma16816(float* d, const uint32_t* a, const uint32_t* b) {
    asm volatile(
        "mma.sync.aligned.m16n8k16.row.col.f32.bf16.bf16.f32 "
        "{%0,%1,%2,%3}, {%4,%5,%6,%7}, {%8,%9}, {%0,%1,%2,%3};"
        : "+f"(d[0]), "+f"(d[1]), "+f"(d[2]), "+f"(d[3])
        : "r"(a[0]), "r"(a[1]), "r"(a[2]), "r"(a[3]), "r"(b[0]), "r"(b[1]));
}
__device__ __forceinline__ void ldsm_x4(uint32_t* r, uint32_t addr) {
    asm volatile("ldmatrix.sync.aligned.m8n8.x4.shared.b16 {%0,%1,%2,%3}, [%4];"
        : "=r"(r[0]), "=r"(r[1]), "=r"(r[2]), "=r"(r[3]) : "r"(addr));
}
__device__ __forceinline__ void cpasync16(uint32_t dst, const void* src, int sz) {
    asm volatile("cp.async.ca.shared.global [%0], [%1], 16, %2;" :: "r"(dst), "l"(src), "r"(sz) : "memory");
}
#define CP_COMMIT() asm volatile("cp.async.commit_group;" ::: "memory")
#define CP_WAIT1()  asm volatile("cp.async.wait_group 1;" ::: "memory")
#define CP_WAIT0()  asm volatile("cp.async.wait_group 0;" ::: "memory")

// ---------------- merged conversions ----------------
#define S0 589824u
#define S1 (S0 + 589824u)
#define S2 (S1 + 131072u)
#define S3 (S2 + 8388608u)
#define S4 (S3 + 16384u)
__global__ void convert_all(
    const float* __restrict__ w_ih, const float* __restrict__ w_hh,
    const float* __restrict__ attnw, const float* __restrict__ outw,
    const float* __restrict__ enc,
    __nv_bfloat16* __restrict__ wihh, __nv_bfloat16* __restrict__ wihl,
    __nv_bfloat16* __restrict__ whhh, __nv_bfloat16* __restrict__ whhl,
    __nv_bfloat16* __restrict__ awh,  __nv_bfloat16* __restrict__ awl,
    __nv_bfloat16* __restrict__ owh,  __nv_bfloat16* __restrict__ owl,
    __nv_bfloat16* __restrict__ ench, __nv_bfloat16* __restrict__ encl)
{
    unsigned i = blockIdx.x * 256 + threadIdx.x;
    if (i >= S4) return;
    if (i < S0) {
        split_store(((const float4*)w_ih)[i], wihh, wihl, i);
    } else if (i < S1) {
        unsigned j = i - S0;
        split_store(((const float4*)w_hh)[j], whhh, whhl, j);
    } else if (i < S2) {
        unsigned j = i - S1;
        split_store(((const float4*)attnw)[j], awh, awl, j);
    } else if (i < S3) {
        unsigned j = i - S2;
        split_store(((const float4*)enc)[j], ench, encl, j);
    } else {
        unsigned j = i - S3;
        unsigned r = j >> 7;
        float4 v = make_float4(0.f, 0.f, 0.f, 0.f);
        if (r < NV) v = ((const float4*)outw)[j];
        split_store(v, owh, owl, j);
    }
}

__global__ void transpose_split_kernel(const float* __restrict__ enc,
                                       __nv_bfloat16* __restrict__ th, __nv_bfloat16* __restrict__ tl) {
    __shared__ float tile[32][33];
    int b = blockIdx.z;
    int d0 = blockIdx.x * 32, s0 = blockIdx.y * 32;
    int x = threadIdx.x, y = threadIdx.y;
    #pragma unroll
    for (int i = 0; i < 32; i += 8)
        tile[y + i][x] = enc[((size_t)b * NSE + s0 + y + i) * DD + d0 + x];
    __syncthreads();
    #pragma unroll
    for (int i = 0; i < 32; i += 8) {
        float v = tile[x][y + i];
        __nv_bfloat16 hb = __float2bfloat16_rn(v);
        size_t o = ((size_t)b * DD + d0 + y + i) * NSE + s0 + x;
        th[o] = hb;
        tl[o] = __float2bfloat16_rn(v - __bfloat162float(hb));
    }
}

__global__ void embed_split_kernel(const int* __restrict__ seqs, const float* __restrict__ emb,
                                   __nv_bfloat16* __restrict__ h, __nv_bfloat16* __restrict__ l) {
    size_t i = (size_t)blockIdx.x * blockDim.x + threadIdx.x;
    size_t row = i >> 7;
    int c = (int)(i & 127);
    int tok = seqs[row];
    split_store(((const float4*)(emb + (size_t)tok * DD))[c], h, l, i);
}
__global__ void copy4_kernel(float* __restrict__ dst, const float* __restrict__ src, int n4) {
    int i = blockIdx.x * blockDim.x + threadIdx.x;
    if (i < n4) ((float4*)dst)[i] = ((const float4*)src)[i];
}
__global__ void h_init_kernel(const float* __restrict__ h0, float* __restrict__ hstate,
                              __nv_bfloat16* __restrict__ hh, __nv_bfloat16* __restrict__ hl) {
    int i = blockIdx.x * 256 + threadIdx.x;
    if (i >= NB * DD / 4) return;
    float4 v = ((const float4*)h0)[i];
    ((float4*)hstate)[i] = v;
    split_store(v, hh, hl, i);   // buffer 0 only (t=0 reads buf0)
}
__global__ void softmax_kernel(float* __restrict__ P, __nv_bfloat16* __restrict__ ph,
                               __nv_bfloat16* __restrict__ pl) {
    __shared__ float red[256];
    size_t row = blockIdx.x;
    float* p = P + row * NSE;
    int tid = threadIdx.x;
    float v0 = p[tid], v1 = p[tid + 256];
    red[tid] = fmaxf(v0, v1); __syncthreads();
    #pragma unroll
    for (int s = 128; s > 0; s >>= 1) { if (tid < s) red[tid] = fmaxf(red[tid], red[tid + s]); __syncthreads(); }
    float mx = red[0]; __syncthreads();
    float e0 = __expf(v0 - mx), e1 = __expf(v1 - mx);
    red[tid] = e0 + e1; __syncthreads();
    #pragma unroll
    for (int s = 128; s > 0; s >>= 1) { if (tid < s) red[tid] += red[tid + s]; __syncthreads(); }
    float inv = 1.0f / red[0];
    float o0 = e0 * inv, o1 = e1 * inv;
    p[tid] = o0; p[tid + 256] = o1;
    __nv_bfloat16 b0 = __float2bfloat16_rn(o0), b1 = __float2bfloat16_rn(o1);
    ph[row * NSE + tid] = b0;
    ph[row * NSE + tid + 256] = b1;
    pl[row * NSE + tid] = __float2bfloat16_rn(o0 - __bfloat162float(b0));
    pl[row * NSE + tid + 256] = __float2bfloat16_rn(o1 - __bfloat162float(b1));
}

// ---------------- mma.sync split-bf16 NT GEMM, 2-stage, 2 blocks/SM ----------------
#define LDT 40
#define TILE_B (128 * LDT * 2)
#define STAGE_B (4 * TILE_B)
#define GM_SMEM (2 * STAGE_B)
__global__ void __launch_bounds__(256, 2) gemm_mma(
    const __nv_bfloat16* __restrict__ A0h, const __nv_bfloat16* __restrict__ A0l,
    const __nv_bfloat16* __restrict__ A1h, const __nv_bfloat16* __restrict__ A1l,
    int K0, int K1, int K,
    const __nv_bfloat16* __restrict__ Wh, const __nv_bfloat16* __restrict__ Wl, int nvalid,
    float* __restrict__ C, __nv_bfloat16* __restrict__ Obh, __nv_bfloat16* __restrict__ Obl, int ldc,
    size_t sA, size_t sW, size_t sC,
    float scale, const float* __restrict__ bias, const float* __restrict__ mask, int epi)
{
    uint32_t smb = smem_u32(smf);
    int tid = threadIdx.x, lane = tid & 31, wid = tid >> 5;
    int wm = wid >> 2, wn = wid & 3;
    int bz = blockIdx.z;
    int nBase = blockIdx.x * 128, mBase = blockIdx.y * 128;
    const __nv_bfloat16* a0h = A0h + (size_t)bz * sA;
    const __nv_bfloat16* a0l = A0l + (size_t)bz * sA;
    const __nv_bfloat16* wh  = Wh  + (size_t)bz * sW;
    const __nv_bfloat16* wl  = Wl  + (size_t)bz * sW;
    float* Cb = C + (size_t)bz * sC;
    __nv_bfloat16* obh = Obh + (size_t)bz * sC;
    __nv_bfloat16* obl = Obl + (size_t)bz * sC;

    float acc[4][4][4];
    #pragma unroll
    for (int i = 0; i < 4; i++)
        #pragma unroll
        for (int j = 0; j < 4; j++)
            #pragma unroll
            for (int q = 0; q < 4; q++) acc[i][j][q] = 0.0f;

    auto load_chunk = [&](int buf, int c) {
        int kOff = c * 32;
        const __nv_bfloat16 *ah, *al;
        int lda, ka;
        if (kOff < K0) { ah = a0h; al = a0l; lda = K0; ka = kOff; }
        else           { ah = A1h; al = A1l; lda = K1; ka = kOff - K0; }
        uint32_t sb = smb + buf * STAGE_B;
        #pragma unroll
        for (int p = 0; p < 8; p++) {
            int idx = p * 256 + tid;
            int tile = idx >> 9, rem = idx & 511;
            int r = rem >> 2, c16 = rem & 3;
            uint32_t dst = sb + tile * TILE_B + r * (LDT * 2) + c16 * 16;
            if (tile == 0)      cpasync16(dst, ah + (size_t)(mBase + r) * lda + ka + c16 * 8, 16);
            else if (tile == 1) cpasync16(dst, al + (size_t)(mBase + r) * lda + ka + c16 * 8, 16);
            else if (tile == 2) cpasync16(dst, wh + (size_t)(nBase + r) * K + kOff + c16 * 8, (nBase + r < nvalid) ? 16 : 0);
            else                cpasync16(dst, wl + (size_t)(nBase + r) * K + kOff + c16 * 8, (nBase + r < nvalid) ? 16 : 0);
        }
    };

    int aRow = lane & 15, aK = (lane >> 4) * 8;
    int bRow = (lane & 7) + ((lane >> 4) & 1) * 8, bK = ((lane >> 3) & 1) * 8;

    int nk = K / 32;
    load_chunk(0, 0);
    CP_COMMIT();
    for (int c = 0; c < nk; c++) {
        if (c + 1 < nk) { load_chunk((c + 1) & 1, c + 1); CP_COMMIT(); CP_WAIT1(); }
        else            { CP_WAIT0(); }
        __syncthreads();
        uint32_t sb = smb + (c & 1) * STAGE_B;
        #pragma unroll
        for (int ks = 0; ks < 2; ks++) {
            uint32_t ahf[4][4], alf[4][4];
            #pragma unroll
            for (int mf = 0; mf < 4; mf++) {
                uint32_t ra = sb + ((wm * 64 + mf * 16 + aRow) * LDT + ks * 16 + aK) * 2;
                ldsm_x4(ahf[mf], ra);
                ldsm_x4(alf[mf], ra + TILE_B);
            }
            #pragma unroll
            for (int np = 0; np < 2; np++) {
                uint32_t rb = sb + 2 * TILE_B + ((wn * 32 + np * 16 + bRow) * LDT + ks * 16 + bK) * 2;
                uint32_t bh[4], bl[4];
                ldsm_x4(bh, rb);
                ldsm_x4(bl, rb + TILE_B);
                #pragma unroll
                for (int mf = 0; mf < 4; mf++) {
                    mma16816(acc[mf][np * 2 + 0], ahf[mf], &bh[0]);
                    mma16816(acc[mf][np * 2 + 0], ahf[mf], &bl[0]);
                    mma16816(acc[mf][np * 2 + 0], alf[mf], &bh[0]);
                    mma16816(acc[mf][np * 2 + 1], ahf[mf], &bh[2]);
                    mma16816(acc[mf][np * 2 + 1], ahf[mf], &bl[2]);
                    mma16816(acc[mf][np * 2 + 1], alf[mf], &bh[2]);
                }
            }
        }
        __syncthreads();
    }

    int rOff = lane >> 2, cOff = (lane & 3) * 2;
    #pragma unroll
    for (int mf = 0; mf < 4; mf++) {
        int mrow0 = mBase + wm * 64 + mf * 16 + rOff;
        int mrow1 = mrow0 + 8;
        float mk0 = 1.0f, mk1 = 1.0f;
        if (epi == 2 || epi == 5) {
            mk0 = mask[(size_t)bz * (sC / ldc) + mrow0];
            mk1 = mask[(size_t)bz * (sC / ldc) + mrow1];
        }
        #pragma unroll
        for (int nf = 0; nf < 4; nf++) {
            int col = nBase + wn * 32 + nf * 8 + cOff;
            if (col >= nvalid) continue;
            float v0 = acc[mf][nf][0] * scale, v1 = acc[mf][nf][1] * scale;
            float v2 = acc[mf][nf][2] * scale, v3 = acc[mf][nf][3] * scale;
            if (bias) {
                float b0 = bias[col], b1 = bias[col + 1];
                v0 += b0; v1 += b1; v2 += b0; v3 += b1;
            }
            if (epi == 0) {
                *(float2*)(Cb + (size_t)mrow0 * ldc + col) = make_float2(v0, v1);
                *(float2*)(Cb + (size_t)mrow1 * ldc + col) = make_float2(v2, v3);
            } else if (epi == 2) {
                v0 *= mk0; v1 *= mk0; v2 *= mk1; v3 *= mk1;
                *(float2*)(Cb + (size_t)mrow0 * ldc + col) = make_float2(v0, v1);
                *(float2*)(Cb + (size_t)mrow1 * ldc + col) = make_float2(v2, v3);
            } else {
                if (epi == 5) {
                    v0 = tanh_fast(v0) * mk0; v1 = tanh_fast(v1) * mk0;
                    v2 = tanh_fast(v2) * mk1; v3 = tanh_fast(v3) * mk1;
                }
                __nv_bfloat16 h0 = __float2bfloat16_rn(v0), h1 = __float2bfloat16_rn(v1);
                __nv_bfloat16 h2 = __float2bfloat16_rn(v2), h3 = __float2bfloat16_rn(v3);
                uint32_t hp0 = bfu(h0) | (bfu(h1) << 16);
                uint32_t hp1 = bfu(h2) | (bfu(h3) << 16);
                uint32_t lp0 = bfu(__float2bfloat16_rn(v0 - __bfloat162float(h0))) |
                               (bfu(__float2bfloat16_rn(v1 - __bfloat162float(h1))) << 16);
                uint32_t lp1 = bfu(__float2bfloat16_rn(v2 - __bfloat162float(h2))) |
                               (bfu(__float2bfloat16_rn(v3 - __bfloat162float(h3))) << 16);
                *(uint32_t*)(obh + (size_t)mrow0 * ldc + col) = hp0;
                *(uint32_t*)(obh + (size_t)mrow1 * ldc + col) = hp1;
                *(uint32_t*)(obl + (size_t)mrow0 * ldc + col) = lp0;
                *(uint32_t*)(obl + (size_t)mrow1 * ldc + col) = lp1;
            }
        }
    }
}

// ---------------- per-m-group barrier (32 blocks per group) ----------------
__device__ __forceinline__ void bar4(int grp) {
    __syncthreads();
    if (threadIdx.x == 0) {
        __threadfence();
        unsigned gen = g_gen4[grp];
        unsigned old = atomicAdd(&g_cnt4[grp], 1);
        if (old == 31u) {
            atomicExch(&g_cnt4[grp], 0u);
            __threadfence();
            g_gen4[grp] = gen + 1u;
        } else {
            while (g_gen4[grp] == gen) { }
        }
        __threadfence();
    }
    __syncthreads();
}

// ---------------- persistent tensor-core GRU, gate-interleaved, double-buffered h ----------------
// 128 blocks = 4 m-groups (32 batch rows) x 32 j-tiles (16 j; 48 W rows = 3 gates x 16 j).
// 192 threads = 6 warps (warp_m 0..1, warp_g 0..2). cp.async staging + xp prefetch.
#define LDW 520
#define GRUW_B (48 * LDW * 2)                  // 49920 per W array
#define GRUH_B (32 * LDW * 2)                  // 33280 per h array
#define GBUF_OFF (2 * GRUW_B + 2 * GRUH_B)     // 166400
#define XS_OFF  (GBUF_OFF + 3 * 32 * 16 * 4)   // 172544
#define BS_OFF  (XS_OFF + 3 * 32 * 16 * 4)     // 178688
#define GRU2_SMEM (BS_OFF + 48 * 4)            // 178880
__global__ void __launch_bounds__(192, 1) gru_mma(
    const __nv_bfloat16* __restrict__ Wh, const __nv_bfloat16* __restrict__ Wl,
    const float* __restrict__ bhh, const float* __restrict__ xp,
    float* __restrict__ hstate,
    __nv_bfloat16* __restrict__ hsh, __nv_bfloat16* __restrict__ hsl,
    __nv_bfloat16* __restrict__ yh, __nv_bfloat16* __restrict__ yl,
    float* __restrict__ maskp)
{
    char* sm = (char*)smf;
    uint32_t smb = smem_u32(sm);
    float* gbuf = (float*)(sm + GBUF_OFF);    // [3][32][16]
    float* xsm  = (float*)(sm + XS_OFF);      // [3][32][16]
    float* bsm  = (float*)(sm + BS_OFF);      // [48]
    int tid = threadIdx.x, lane = tid & 31, w = tid >> 5;
    int mb = blockIdx.x >> 5, jb = blockIdx.x & 31;
    int warp_m = w & 1, warp_g = w >> 1;
    int jBase = jb * 16;

    // stage W slice: 48 rows = gate g, local jj -> global row g*512 + jBase + jj
    for (int idx = tid; idx < 48 * 64; idx += 192) {
        int r = idx >> 6, c = idx & 63;
        int g = r >> 4, jj = r & 15;
        size_t grow = (size_t)(g * DD + jBase + jj);
        *(uint4*)(sm + r * (LDW * 2) + c * 16) = *(const uint4*)(Wh + grow * DD + c * 8);
        *(uint4*)(sm + GRUW_B + r * (LDW * 2) + c * 16) = *(const uint4*)(Wl + grow * DD + c * 8);
    }
    // bias: 3 gates x 16 j
    if (tid < 48) bsm[tid] = bhh[(tid >> 4) * DD + jBase + (tid & 15)];

    int aRow = lane & 15, aK = (lane >> 4) * 8;
    int bRow = (lane & 7) + ((lane >> 4) & 1) * 8, bK = ((lane >> 3) & 1) * 8;
    uint32_t wb_h = smb + ((warp_g * 16 + bRow) * LDW + bK) * 2;
    uint32_t wb_l = wb_h + GRUW_B;
    uint32_t hb_h = smb + 2 * GRUW_B + ((warp_m * 16 + aRow) * LDW + aK) * 2;
    uint32_t hb_l = hb_h + GRUH_B;

    for (int t = 0; t < NS; t++) {
        const __nv_bfloat16* hr = hsh + (size_t)(t & 1) * NB * DD;
        const __nv_bfloat16* lr = hsl + (size_t)(t & 1) * NB * DD;
        __nv_bfloat16* hw = hsh + (size_t)((t + 1) & 1) * NB * DD;
        __nv_bfloat16* lw = hsl + (size_t)((t + 1) & 1) * NB * DD;

        // cp.async: stage h(t) hi/lo + prefetch xp(t) slice
        for (int idx = tid; idx < 32 * 64; idx += 192) {
            int r = idx >> 6, c = idx & 63;
            cpasync16(smb + 2 * GRUW_B + r * (LDW * 2) + c * 16,
                      hr + (size_t)(mb * 32 + r) * DD + c * 8, 16);
            cpasync16(smb + 2 * GRUW_B + GRUH_B + r * (LDW * 2) + c * 16,
                      lr + (size_t)(mb * 32 + r) * DD + c * 8, 16);
        }
        for (int idx = tid; idx < 384; idx += 192) {
            int gm = idx >> 2, q = idx & 3;         // gm = g*32 + m_loc
            int g = gm >> 5, m_loc = gm & 31;
            int b = mb * 32 + m_loc;
            cpasync16(smb + XS_OFF + (gm * 16 + q * 4) * 4,
                      xp + ((size_t)b * NS + t) * D3 + g * DD + jBase + q * 4, 16);
        }
        CP_COMMIT();
        CP_WAIT0();
        __syncthreads();

        float acc0[4] = {0, 0, 0, 0}, acc1[4] = {0, 0, 0, 0};
        #pragma unroll 4
        for (int kc = 0; kc < 32; kc++) {
            uint32_t ah[4], al[4], bh[4], bl[4];
            ldsm_x4(ah, hb_h + kc * 32);
            ldsm_x4(al, hb_l + kc * 32);
            ldsm_x4(bh, wb_h + kc * 32);
            ldsm_x4(bl, wb_l + kc * 32);
            mma16816(acc0, ah, &bh[0]);
            mma16816(acc0, ah, &bl[0]);
            mma16816(acc0, al, &bh[0]);
            mma16816(acc1, ah, &bh[2]);
            mma16816(acc1, ah, &bl[2]);
            mma16816(acc1, al, &bh[2]);
        }

        // gate slice into gbuf[warp_g][m][j]
        {
            int m0 = warp_m * 16 + (lane >> 2);
            int jc = (lane & 3) * 2;
            float* gb = gbuf + (warp_g * 32 + m0) * 16;
            gb[jc] = acc0[0];     gb[jc + 1] = acc0[1];
            gb[jc + 8] = acc1[0]; gb[jc + 9] = acc1[1];
            gb += 8 * 16;
            gb[jc] = acc0[2];     gb[jc + 1] = acc0[3];
            gb[jc + 8] = acc1[2]; gb[jc + 9] = acc1[3];
        }
        __syncthreads();

        // local pointwise
        for (int idx = tid; idx < 512; idx += 192) {
            int m_loc = idx >> 4, j_loc = idx & 15;
            int b = mb * 32 + m_loc;
            int j = jBase + j_loc;
            float gr = gbuf[(0 * 32 + m_loc) * 16 + j_loc];
            float gz = gbuf[(1 * 32 + m_loc) * 16 + j_loc];
            float gn = gbuf[(2 * 32 + m_loc) * 16 + j_loc];
            float xr = xsm[(0 * 32 + m_loc) * 16 + j_loc];
            float xz = xsm[(1 * 32 + m_loc) * 16 + j_loc];
            float xn = xsm[(2 * 32 + m_loc) * 16 + j_loc];
            float r = sigmoid_fast(xr + gr + bsm[j_loc]);
            float z = sigmoid_fast(xz + gz + bsm[16 + j_loc]);
            float n = tanh_fast(xn + r * (gn + bsm[32 + j_loc]));
            float hp = hstate[(size_t)b * DD + j];
            float h2 = (1.0f - z) * n + z * hp;
            hstate[(size_t)b * DD + j] = h2;
            __nv_bfloat16 hb16 = __float2bfloat16_rn(h2);
            __nv_bfloat16 lb16 = __float2bfloat16_rn(h2 - __bfloat162float(hb16));
            hw[(size_t)b * DD + j] = hb16;
            lw[(size_t)b * DD + j] = lb16;
            size_t yi = ((size_t)b * NS + t) * DD + j;
            yh[yi] = hb16;
            yl[yi] = lb16;
            if (j == 0) maskp[(size_t)b * NS + t] = (h2 != 0.0f) ? 1.0f : 0.0f;
        }
        bar4(mb);
    }
}

extern "C" void kernel_launch(void* const* d_in, const int* in_sizes, int n_in,
                              void* d_out, int out_size) {
    const int*   seqs  = (const int*)d_in[0];
    const float* enc   = (const float*)d_in[2];
    const float* h0    = (const float*)d_in[3];
    const float* emb   = (const float*)d_in[4];
    const float* w_ih  = (const float*)d_in[5];
    const float* w_hh  = (const float*)d_in[6];
    const float* b_ih  = (const float*)d_in[7];
    const float* b_hh  = (const float*)d_in[8];
    const float* attnw = (const float*)d_in[9];
    const float* attnb = (const float*)d_in[10];
    const float* outw  = (const float*)d_in[11];
    const float* outb  = (const float*)d_in[12];
    float* out = (float*)d_out;

    float *xp, *hstate, *mask;
    __nv_bfloat16 *hsh, *hsl, *Ah, *Al, *Ph, *Pl, *Ch, *Cl, *Dh, *Dl;
    __nv_bfloat16 *ench, *encl, *encTh, *encTl, *wihh, *wihl, *whhh, *whhl, *awh, *awl, *owh, *owl;
    cudaGetSymbolAddress((void**)&xp,     g_xp);
    cudaGetSymbolAddress((void**)&hstate, g_h);
    cudaGetSymbolAddress((void**)&mask,   g_mask);
    cudaGetSymbolAddress((void**)&hsh, g_hsh);     cudaGetSymbolAddress((void**)&hsl, g_hsl);
    cudaGetSymbolAddress((void**)&Ah, g_Ah);   cudaGetSymbolAddress((void**)&Al, g_Al);
    cudaGetSymbolAddress((void**)&Ph, g_Ph);   cudaGetSymbolAddress((void**)&Pl, g_Pl);
    cudaGetSymbolAddress((void**)&Ch, g_Ch);   cudaGetSymbolAddress((void**)&Cl, g_Cl);
    cudaGetSymbolAddress((void**)&Dh, g_Dh);   cudaGetSymbolAddress((void**)&Dl, g_Dl);
    cudaGetSymbolAddress((void**)&ench, g_ench);   cudaGetSymbolAddress((void**)&encl, g_encl);
    cudaGetSymbolAddress((void**)&encTh, g_encTh); cudaGetSymbolAddress((void**)&encTl, g_encTl);
    cudaGetSymbolAddress((void**)&wihh, g_wihh);   cudaGetSymbolAddress((void**)&wihl, g_wihl);
    cudaGetSymbolAddress((void**)&whhh, g_whhh);   cudaGetSymbolAddress((void**)&whhl, g_whhl);
    cudaGetSymbolAddress((void**)&awh, g_awh);     cudaGetSymbolAddress((void**)&awl, g_awl);
    cudaGetSymbolAddress((void**)&owh, g_owh);     cudaGetSymbolAddress((void**)&owl, g_owl);

    static int attr_set = 0;
    if (!attr_set) {
        cudaFuncSetAttribute(gru_mma, cudaFuncAttributeMaxDynamicSharedMemorySize, GRU2_SMEM);
        cudaFuncSetAttribute(gemm_mma, cudaFuncAttributeMaxDynamicSharedMemorySize, GM_SMEM);
        attr_set = 1;
    }

    const size_t OUT_H    = (size_t)MALL * NV;
    const size_t OUT_ATTN = OUT_H + (size_t)NL * NB * DD;
    float* attnP = out + OUT_ATTN;
    const float SC = 0.044194173824159216f;

    convert_all<<<(S4 + 255) / 256, 256>>>(
        w_ih, w_hh, attnw, outw, enc,
        wihh, wihl, whhh, whhl, awh, awl, owh, owl, ench, encl);
    transpose_split_kernel<<<dim3(16, 16, 128), dim3(32, 8)>>>(enc, encTh, encTl);
    embed_split_kernel<<<(MALL * (DD / 4)) / 256, 256>>>(seqs, emb, Ah, Al);

    for (int l = 0; l < NL; l++) {
        gemm_mma<<<dim3(12, 512, 1), 256, GM_SMEM>>>(
            Ah, Al, nullptr, nullptr, DD, DD, DD,
            wihh + (size_t)l * D3 * DD, wihl + (size_t)l * D3 * DD, D3,
            xp, nullptr, nullptr, D3, 0, 0, 0, 1.0f, b_ih + (size_t)l * D3, nullptr, 0);
        h_init_kernel<<<(NB * DD / 4 + 255) / 256, 256>>>(
            h0 + (size_t)l * NB * DD, hstate, hsh, hsl);
        gru_mma<<<128, 192, GRU2_SMEM>>>(
            whhh + (size_t)l * D3 * DD, whhl + (size_t)l * D3 * DD,
            b_hh + (size_t)l * D3, xp, hstate, hsh, hsl, Ah, Al, mask);
        copy4_kernel<<<64, 256>>>(out + OUT_H + (size_t)l * NB * DD, hstate, NB * DD / 4);
    }

    gemm_mma<<<dim3(4, 4, 128), 256, GM_SMEM>>>(
        Ah, Al, nullptr, nullptr, DD, DD, DD,
        ench, encl, NSE,
        attnP, nullptr, nullptr, NSE, (size_t)NS * DD, (size_t)NSE * DD, (size_t)NS * NSE,
        SC, nullptr, nullptr, 0);
    softmax_kernel<<<MALL, 256>>>(attnP, Ph, Pl);

    gemm_mma<<<dim3(4, 4, 128), 256, GM_SMEM>>>(
        Ph, Pl, nullptr, nullptr, NSE, NSE, NSE,
        encTh, encTl, DD,
        nullptr, Ch, Cl, DD, (size_t)NS * NSE, (size_t)DD * NSE, (size_t)NS * DD,
        1.0f, nullptr, nullptr, 4);

    gemm_mma<<<dim3(4, 512, 1), 256, GM_SMEM>>>(
        Ah, Al, Ch, Cl, DD, DD, 2 * DD,
        awh, awl, DD,
        nullptr, Dh, Dl, DD, 0, 0, 0, 1.0f, attnb, mask, 5);

    gemm_mma<<<dim3(1, 512, 1), 256, GM_SMEM>>>(
        Dh, Dl, nullptr, nullptr, DD, DD, DD,
        owh, owl, NV,
        out, nullptr, nullptr, NV, 0, 0, 0, 1.0f, outb, mask, 2);
}

// round 15
// speedup vs baseline: 1.7221x; 1.0953x over previous
#include <cuda_runtime.h>
#include <cuda_bf16.h>
#include <math.h>
#include <stdint.h>

#define NL 3
#define DD 512
#define NV 100
#define NB 128
#define NS 512
#define NSE 512
#define MALL (NB*NS)
#define D3 (3*DD)

// ---------------- scratch ----------------
__device__ float g_xp[(size_t)MALL * D3];
__device__ float g_h[NB * DD];
__device__ float g_mask[MALL];
__device__ unsigned g_cnt4[4];
__device__ volatile unsigned g_gen4[4];
__device__ __nv_bfloat16 g_hsh[2 * NB * DD];
__device__ __nv_bfloat16 g_hsl[2 * NB * DD];
__device__ __nv_bfloat16 g_Ah[(size_t)MALL * DD];
__device__ __nv_bfloat16 g_Al[(size_t)MALL * DD];
__device__ __nv_bfloat16 g_Ph[(size_t)MALL * NSE];
__device__ __nv_bfloat16 g_Pl[(size_t)MALL * NSE];
__device__ __nv_bfloat16 g_Ch[(size_t)MALL * DD];
__device__ __nv_bfloat16 g_Cl[(size_t)MALL * DD];
__device__ __nv_bfloat16 g_Dh[(size_t)MALL * DD];
__device__ __nv_bfloat16 g_Dl[(size_t)MALL * DD];
__device__ __nv_bfloat16 g_ench[(size_t)NB * NSE * DD];
__device__ __nv_bfloat16 g_encl[(size_t)NB * NSE * DD];
__device__ __nv_bfloat16 g_encTh[(size_t)NB * DD * NSE];
__device__ __nv_bfloat16 g_encTl[(size_t)NB * DD * NSE];
__device__ __nv_bfloat16 g_wihh[(size_t)NL * D3 * DD];
__device__ __nv_bfloat16 g_wihl[(size_t)NL * D3 * DD];
__device__ __nv_bfloat16 g_whhh[(size_t)NL * D3 * DD];
__device__ __nv_bfloat16 g_whhl[(size_t)NL * D3 * DD];
__device__ __nv_bfloat16 g_awh[(size_t)DD * 2 * DD];
__device__ __nv_bfloat16 g_awl[(size_t)DD * 2 * DD];
__device__ __nv_bfloat16 g_owh[128 * DD];
__device__ __nv_bfloat16 g_owl[128 * DD];

extern __shared__ float smf[];

// ---------------- helpers ----------------
__device__ __forceinline__ float tanh_fast(float x) {
    float y;
    asm("tanh.approx.f32 %0, %1;" : "=f"(y) : "f"(x));
    return y;
}
__device__ __forceinline__ float sigmoid_fast(float x) { return 1.0f / (1.0f + __expf(-x)); }
__device__ __forceinline__ uint32_t smem_u32(const void* p) {
    uint32_t a;
    asm("{ .reg .u64 t; cvta.to.shared.u64 t, %1; cvt.u32.u64 %0, t; }" : "=r"(a) : "l"(p));
    return a;
}
__device__ __forceinline__ unsigned bfu(__nv_bfloat16 b) {
    unsigned short s = __bfloat16_as_ushort(b);
    return (unsigned)s;
}
__device__ __forceinline__ void split_store(float4 v, __nv_bfloat16* h, __nv_bfloat16* l, size_t i4) {
    __nv_bfloat16 h0 = __float2bfloat16_rn(v.x), h1 = __float2bfloat16_rn(v.y);
    __nv_bfloat16 h2 = __float2bfloat16_rn(v.z), h3 = __float2bfloat16_rn(v.w);
    uint2 hv, lv;
    hv.x = bfu(h0) | (bfu(h1) << 16); hv.y = bfu(h2) | (bfu(h3) << 16);
    lv.x = bfu(__float2bfloat16_rn(v.x - __bfloat162float(h0))) |
           (bfu(__float2bfloat16_rn(v.y - __bfloat162float(h1))) << 16);
    lv.y = bfu(__float2bfloat16_rn(v.z - __bfloat162float(h2))) |
           (bfu(__float2bfloat16_rn(v.w - __bfloat162float(h3))) << 16);
    ((uint2*)h)[i4] = hv; ((uint2*)l)[i4] = lv;
}

// ---------------- mma.sync primitives ----------------
__device__ __forceinline__ void mma16816(float* d, const uint32_t* a, const uint32_t* b) {
    asm volatile(
        "mma.sync.aligned.m16n8k16.row.col.f32.bf16.bf16.f32 "
        "{%0,%1,%2,%3}, {%4,%5,%6,%7}, {%8,%9}, {%0,%1,%2,%3};"
        : "+f"(d[0]), "+f"(d[1]), "+f"(d[2]), "+f"(d[3])
        : "r"(a[0]), "r"(a[1]), "r"(a[2]), "r"(a[3]), "r"(b[0]), "r"(b[1]));
}
__device__ __forceinline__ void ldsm_x4(uint32_t* r, uint32_t addr) {
    asm volatile("ldmatrix.sync.aligned.m8n8.x4.shared.b16 {%0,%1,%2,%3}, [%4];"
        : "=r"(r[0]), "=r"(r[1]), "=r"(r[2]), "=r"(r[3]) : "r"(addr));
}
__device__ __forceinline__ void cpasync16(uint32_t dst, const void* src, int sz) {
    asm volatile("cp.async.ca.shared.global [%0], [%1], 16, %2;" :: "r"(dst), "l"(src), "r"(sz) : "memory");
}
#define CP_COMMIT() asm volatile("cp.async.commit_group;" ::: "memory")
#define CP_WAIT1()  asm volatile("cp.async.wait_group 1;" ::: "memory")
#define CP_WAIT0()  asm volatile("cp.async.wait_group 0;" ::: "memory")

// ---------------- merged conversions ----------------
#define S0 589824u
#define S1 (S0 + 589824u)
#define S2 (S1 + 131072u)
#define S3 (S2 + 8388608u)
#define S4 (S3 + 16384u)
__global__ void convert_all(
    const float* __restrict__ w_ih, const float* __restrict__ w_hh,
    const float* __restrict__ attnw, const float* __restrict__ outw,
    const float* __restrict__ enc,
    __nv_bfloat16* __restrict__ wihh, __nv_bfloat16* __restrict__ wihl,
    __nv_bfloat16* __restrict__ whhh, __nv_bfloat16* __restrict__ whhl,
    __nv_bfloat16* __restrict__ awh,  __nv_bfloat16* __restrict__ awl,
    __nv_bfloat16* __restrict__ owh,  __nv_bfloat16* __restrict__ owl,
    __nv_bfloat16* __restrict__ ench, __nv_bfloat16* __restrict__ encl)
{
    unsigned i = blockIdx.x * 256 + threadIdx.x;
    if (i >= S4) return;
    if (i < S0) {
        split_store(((const float4*)w_ih)[i], wihh, wihl, i);
    } else if (i < S1) {
        unsigned j = i - S0;
        split_store(((const float4*)w_hh)[j], whhh, whhl, j);
    } else if (i < S2) {
        unsigned j = i - S1;
        split_store(((const float4*)attnw)[j], awh, awl, j);
    } else if (i < S3) {
        unsigned j = i - S2;
        split_store(((const float4*)enc)[j], ench, encl, j);
    } else {
        unsigned j = i - S3;
        unsigned r = j >> 7;
        float4 v = make_float4(0.f, 0.f, 0.f, 0.f);
        if (r < NV) v = ((const float4*)outw)[j];
        split_store(v, owh, owl, j);
    }
}

__global__ void transpose_split_kernel(const float* __restrict__ enc,
                                       __nv_bfloat16* __restrict__ th, __nv_bfloat16* __restrict__ tl) {
    __shared__ float tile[32][33];
    int b = blockIdx.z;
    int d0 = blockIdx.x * 32, s0 = blockIdx.y * 32;
    int x = threadIdx.x, y = threadIdx.y;
    #pragma unroll
    for (int i = 0; i < 32; i += 8)
        tile[y + i][x] = enc[((size_t)b * NSE + s0 + y + i) * DD + d0 + x];
    __syncthreads();
    #pragma unroll
    for (int i = 0; i < 32; i += 8) {
        float v = tile[x][y + i];
        __nv_bfloat16 hb = __float2bfloat16_rn(v);
        size_t o = ((size_t)b * DD + d0 + y + i) * NSE + s0 + x;
        th[o] = hb;
        tl[o] = __float2bfloat16_rn(v - __bfloat162float(hb));
    }
}

__global__ void embed_split_kernel(const int* __restrict__ seqs, const float* __restrict__ emb,
                                   __nv_bfloat16* __restrict__ h, __nv_bfloat16* __restrict__ l) {
    size_t i = (size_t)blockIdx.x * blockDim.x + threadIdx.x;
    size_t row = i >> 7;
    int c = (int)(i & 127);
    int tok = seqs[row];
    split_store(((const float4*)(emb + (size_t)tok * DD))[c], h, l, i);
}
__global__ void copy4_kernel(float* __restrict__ dst, const float* __restrict__ src, int n4) {
    int i = blockIdx.x * blockDim.x + threadIdx.x;
    if (i < n4) ((float4*)dst)[i] = ((const float4*)src)[i];
}
__global__ void h_init_kernel(const float* __restrict__ h0, float* __restrict__ hstate,
                              __nv_bfloat16* __restrict__ hh, __nv_bfloat16* __restrict__ hl) {
    int i = blockIdx.x * 256 + threadIdx.x;
    if (i >= NB * DD / 4) return;
    float4 v = ((const float4*)h0)[i];
    ((float4*)hstate)[i] = v;
    split_store(v, hh, hl, i);
}
__global__ void softmax_kernel(float* __restrict__ P, __nv_bfloat16* __restrict__ ph,
                               __nv_bfloat16* __restrict__ pl) {
    __shared__ float red[256];
    size_t row = blockIdx.x;
    float* p = P + row * NSE;
    int tid = threadIdx.x;
    float v0 = p[tid], v1 = p[tid + 256];
    red[tid] = fmaxf(v0, v1); __syncthreads();
    #pragma unroll
    for (int s = 128; s > 0; s >>= 1) { if (tid < s) red[tid] = fmaxf(red[tid], red[tid + s]); __syncthreads(); }
    float mx = red[0]; __syncthreads();
    float e0 = __expf(v0 - mx), e1 = __expf(v1 - mx);
    red[tid] = e0 + e1; __syncthreads();
    #pragma unroll
    for (int s = 128; s > 0; s >>= 1) { if (tid < s) red[tid] += red[tid + s]; __syncthreads(); }
    float inv = 1.0f / red[0];
    float o0 = e0 * inv, o1 = e1 * inv;
    p[tid] = o0; p[tid + 256] = o1;
    __nv_bfloat16 b0 = __float2bfloat16_rn(o0), b1 = __float2bfloat16_rn(o1);
    ph[row * NSE + tid] = b0;
    ph[row * NSE + tid + 256] = b1;
    pl[row * NSE + tid] = __float2bfloat16_rn(o0 - __bfloat162float(b0));
    pl[row * NSE + tid + 256] = __float2bfloat16_rn(o1 - __bfloat162float(b1));
}

// ---------------- mma.sync split-bf16 NT GEMM, 2-stage, 2 blocks/SM ----------------
#define LDT 40
#define TILE_B (128 * LDT * 2)
#define STAGE_B (4 * TILE_B)
#define GM_SMEM (2 * STAGE_B)
__global__ void __launch_bounds__(256, 2) gemm_mma(
    const __nv_bfloat16* __restrict__ A0h, const __nv_bfloat16* __restrict__ A0l,
    const __nv_bfloat16* __restrict__ A1h, const __nv_bfloat16* __restrict__ A1l,
    int K0, int K1, int K,
    const __nv_bfloat16* __restrict__ Wh, const __nv_bfloat16* __restrict__ Wl, int nvalid,
    float* __restrict__ C, __nv_bfloat16* __restrict__ Obh, __nv_bfloat16* __restrict__ Obl, int ldc,
    size_t sA, size_t sW, size_t sC,
    float scale, const float* __restrict__ bias, const float* __restrict__ mask, int epi)
{
    uint32_t smb = smem_u32(smf);
    int tid = threadIdx.x, lane = tid & 31, wid = tid >> 5;
    int wm = wid >> 2, wn = wid & 3;
    int bz = blockIdx.z;
    int nBase = blockIdx.x * 128, mBase = blockIdx.y * 128;
    const __nv_bfloat16* a0h = A0h + (size_t)bz * sA;
    const __nv_bfloat16* a0l = A0l + (size_t)bz * sA;
    const __nv_bfloat16* wh  = Wh  + (size_t)bz * sW;
    const __nv_bfloat16* wl  = Wl  + (size_t)bz * sW;
    float* Cb = C + (size_t)bz * sC;
    __nv_bfloat16* obh = Obh + (size_t)bz * sC;
    __nv_bfloat16* obl = Obl + (size_t)bz * sC;

    float acc[4][4][4];
    #pragma unroll
    for (int i = 0; i < 4; i++)
        #pragma unroll
        for (int j = 0; j < 4; j++)
            #pragma unroll
            for (int q = 0; q < 4; q++) acc[i][j][q] = 0.0f;

    auto load_chunk = [&](int buf, int c) {
        int kOff = c * 32;
        const __nv_bfloat16 *ah, *al;
        int lda, ka;
        if (kOff < K0) { ah = a0h; al = a0l; lda = K0; ka = kOff; }
        else           { ah = A1h; al = A1l; lda = K1; ka = kOff - K0; }
        uint32_t sb = smb + buf * STAGE_B;
        #pragma unroll
        for (int p = 0; p < 8; p++) {
            int idx = p * 256 + tid;
            int tile = idx >> 9, rem = idx & 511;
            int r = rem >> 2, c16 = rem & 3;
            uint32_t dst = sb + tile * TILE_B + r * (LDT * 2) + c16 * 16;
            if (tile == 0)      cpasync16(dst, ah + (size_t)(mBase + r) * lda + ka + c16 * 8, 16);
            else if (tile == 1) cpasync16(dst, al + (size_t)(mBase + r) * lda + ka + c16 * 8, 16);
            else if (tile == 2) cpasync16(dst, wh + (size_t)(nBase + r) * K + kOff + c16 * 8, (nBase + r < nvalid) ? 16 : 0);
            else                cpasync16(dst, wl + (size_t)(nBase + r) * K + kOff + c16 * 8, (nBase + r < nvalid) ? 16 : 0);
        }
    };

    int aRow = lane & 15, aK = (lane >> 4) * 8;
    int bRow = (lane & 7) + ((lane >> 4) & 1) * 8, bK = ((lane >> 3) & 1) * 8;

    int nk = K / 32;
    load_chunk(0, 0);
    CP_COMMIT();
    for (int c = 0; c < nk; c++) {
        if (c + 1 < nk) { load_chunk((c + 1) & 1, c + 1); CP_COMMIT(); CP_WAIT1(); }
        else            { CP_WAIT0(); }
        __syncthreads();
        uint32_t sb = smb + (c & 1) * STAGE_B;
        #pragma unroll
        for (int ks = 0; ks < 2; ks++) {
            uint32_t ahf[4][4], alf[4][4];
            #pragma unroll
            for (int mf = 0; mf < 4; mf++) {
                uint32_t ra = sb + ((wm * 64 + mf * 16 + aRow) * LDT + ks * 16 + aK) * 2;
                ldsm_x4(ahf[mf], ra);
                ldsm_x4(alf[mf], ra + TILE_B);
            }
            #pragma unroll
            for (int np = 0; np < 2; np++) {
                uint32_t rb = sb + 2 * TILE_B + ((wn * 32 + np * 16 + bRow) * LDT + ks * 16 + bK) * 2;
                uint32_t bh[4], bl[4];
                ldsm_x4(bh, rb);
                ldsm_x4(bl, rb + TILE_B);
                #pragma unroll
                for (int mf = 0; mf < 4; mf++) {
                    mma16816(acc[mf][np * 2 + 0], ahf[mf], &bh[0]);
                    mma16816(acc[mf][np * 2 + 0], ahf[mf], &bl[0]);
                    mma16816(acc[mf][np * 2 + 0], alf[mf], &bh[0]);
                    mma16816(acc[mf][np * 2 + 1], ahf[mf], &bh[2]);
                    mma16816(acc[mf][np * 2 + 1], ahf[mf], &bl[2]);
                    mma16816(acc[mf][np * 2 + 1], alf[mf], &bh[2]);
                }
            }
        }
        __syncthreads();
    }

    int rOff = lane >> 2, cOff = (lane & 3) * 2;
    #pragma unroll
    for (int mf = 0; mf < 4; mf++) {
        int mrow0 = mBase + wm * 64 + mf * 16 + rOff;
        int mrow1 = mrow0 + 8;
        float mk0 = 1.0f, mk1 = 1.0f;
        if (epi == 2 || epi == 5) {
            mk0 = mask[(size_t)bz * (sC / ldc) + mrow0];
            mk1 = mask[(size_t)bz * (sC / ldc) + mrow1];
        }
        #pragma unroll
        for (int nf = 0; nf < 4; nf++) {
            int col = nBase + wn * 32 + nf * 8 + cOff;
            if (col >= nvalid) continue;
            float v0 = acc[mf][nf][0] * scale, v1 = acc[mf][nf][1] * scale;
            float v2 = acc[mf][nf][2] * scale, v3 = acc[mf][nf][3] * scale;
            if (bias) {
                float b0 = bias[col], b1 = bias[col + 1];
                v0 += b0; v1 += b1; v2 += b0; v3 += b1;
            }
            if (epi == 0) {
                *(float2*)(Cb + (size_t)mrow0 * ldc + col) = make_float2(v0, v1);
                *(float2*)(Cb + (size_t)mrow1 * ldc + col) = make_float2(v2, v3);
            } else if (epi == 2) {
                v0 *= mk0; v1 *= mk0; v2 *= mk1; v3 *= mk1;
                *(float2*)(Cb + (size_t)mrow0 * ldc + col) = make_float2(v0, v1);
                *(float2*)(Cb + (size_t)mrow1 * ldc + col) = make_float2(v2, v3);
            } else {
                if (epi == 5) {
                    v0 = tanh_fast(v0) * mk0; v1 = tanh_fast(v1) * mk0;
                    v2 = tanh_fast(v2) * mk1; v3 = tanh_fast(v3) * mk1;
                }
                __nv_bfloat16 h0 = __float2bfloat16_rn(v0), h1 = __float2bfloat16_rn(v1);
                __nv_bfloat16 h2 = __float2bfloat16_rn(v2), h3 = __float2bfloat16_rn(v3);
                uint32_t hp0 = bfu(h0) | (bfu(h1) << 16);
                uint32_t hp1 = bfu(h2) | (bfu(h3) << 16);
                uint32_t lp0 = bfu(__float2bfloat16_rn(v0 - __bfloat162float(h0))) |
                               (bfu(__float2bfloat16_rn(v1 - __bfloat162float(h1))) << 16);
                uint32_t lp1 = bfu(__float2bfloat16_rn(v2 - __bfloat162float(h2))) |
                               (bfu(__float2bfloat16_rn(v3 - __bfloat162float(h3))) << 16);
                *(uint32_t*)(obh + (size_t)mrow0 * ldc + col) = hp0;
                *(uint32_t*)(obh + (size_t)mrow1 * ldc + col) = hp1;
                *(uint32_t*)(obl + (size_t)mrow0 * ldc + col) = lp0;
                *(uint32_t*)(obl + (size_t)mrow1 * ldc + col) = lp1;
            }
        }
    }
}

// ---------------- per-m-group barrier (32 blocks per group) ----------------
__device__ __forceinline__ void bar4(int grp) {
    __syncthreads();
    if (threadIdx.x == 0) {
        __threadfence();
        unsigned gen = g_gen4[grp];
        unsigned old = atomicAdd(&g_cnt4[grp], 1);
        if (old == 31u) {
            atomicExch(&g_cnt4[grp], 0u);
            __threadfence();
            g_gen4[grp] = gen + 1u;
        } else {
            while (g_gen4[grp] == gen) { }
        }
        __threadfence();
    }
    __syncthreads();
}

// ---------------- persistent tensor-core GRU ----------------
// 128 blocks = 4 m-groups x 32 j-tiles. 192 threads (2m x 3g warps).
// h-state f32 resident in smem for all 512 steps; xp prefetched (double buffer).
#define LDW 520
#define GRUW_B (48 * LDW * 2)                  // 49920 per W array
#define GRUH_B (32 * LDW * 2)                  // 33280 per h array
#define GBUF_OFF (2 * GRUW_B + 2 * GRUH_B)     // 166400
#define XS_OFF  (GBUF_OFF + 1536 * 4)          // 172544 (gbuf 6144)
#define HST_OFF (XS_OFF + 2 * 1536 * 4)        // 184832 (xsm 12288)
#define BS_OFF  (HST_OFF + 512 * 4)            // 186880
#define GRU2_SMEM (BS_OFF + 48 * 4)            // 187072
__global__ void __launch_bounds__(192, 1) gru_mma(
    const __nv_bfloat16* __restrict__ Wh, const __nv_bfloat16* __restrict__ Wl,
    const float* __restrict__ bhh, const float* __restrict__ xp,
    float* __restrict__ hstate,
    __nv_bfloat16* __restrict__ hsh, __nv_bfloat16* __restrict__ hsl,
    __nv_bfloat16* __restrict__ yh, __nv_bfloat16* __restrict__ yl,
    float* __restrict__ maskp, int wmask)
{
    char* sm = (char*)smf;
    uint32_t smb = smem_u32(sm);
    float* gbuf = (float*)(sm + GBUF_OFF);    // [3][32][16]
    float* xsm  = (float*)(sm + XS_OFF);      // [2][3][32][16]
    float* hst  = (float*)(sm + HST_OFF);     // [32][16]
    float* bsm  = (float*)(sm + BS_OFF);      // [48]
    int tid = threadIdx.x, lane = tid & 31, w = tid >> 5;
    int mb = blockIdx.x >> 5, jb = blockIdx.x & 31;
    int warp_m = w & 1, warp_g = w >> 1;
    int jBase = jb * 16;

    // stage W slice (gate-interleaved) once
    for (int idx = tid; idx < 48 * 64; idx += 192) {
        int r = idx >> 6, c = idx & 63;
        int g = r >> 4, jj = r & 15;
        size_t grow = (size_t)(g * DD + jBase + jj);
        *(uint4*)(sm + r * (LDW * 2) + c * 16) = *(const uint4*)(Wh + grow * DD + c * 8);
        *(uint4*)(sm + GRUW_B + r * (LDW * 2) + c * 16) = *(const uint4*)(Wl + grow * DD + c * 8);
    }
    if (tid < 48) bsm[tid] = bhh[(tid >> 4) * DD + jBase + (tid & 15)];
    // h-state slice into smem (owned exclusively by this block)
    for (int idx = tid; idx < 512; idx += 192) {
        int m_loc = idx >> 4, j_loc = idx & 15;
        hst[idx] = hstate[(size_t)(mb * 32 + m_loc) * DD + jBase + j_loc];
    }

    auto fetch_xp = [&](int t, int buf) {
        for (int idx = tid; idx < 384; idx += 192) {
            int gm = idx >> 2, q = idx & 3;
            int g = gm >> 5, m_loc = gm & 31;
            int b = mb * 32 + m_loc;
            cpasync16(smb + XS_OFF + (buf * 1536 + gm * 16 + q * 4) * 4,
                      xp + ((size_t)b * NS + t) * D3 + g * DD + jBase + q * 4, 16);
        }
    };
    fetch_xp(0, 0);
    CP_COMMIT();

    int aRow = lane & 15, aK = (lane >> 4) * 8;
    int bRow = (lane & 7) + ((lane >> 4) & 1) * 8, bK = ((lane >> 3) & 1) * 8;
    uint32_t wb_h = smb + ((warp_g * 16 + bRow) * LDW + bK) * 2;
    uint32_t wb_l = wb_h + GRUW_B;
    uint32_t hb_h = smb + 2 * GRUW_B + ((warp_m * 16 + aRow) * LDW + aK) * 2;
    uint32_t hb_l = hb_h + GRUH_B;

    for (int t = 0; t < NS; t++) {
        const __nv_bfloat16* hr = hsh + (size_t)(t & 1) * NB * DD;
        const __nv_bfloat16* lr = hsl + (size_t)(t & 1) * NB * DD;
        __nv_bfloat16* hw = hsh + (size_t)((t + 1) & 1) * NB * DD;
        __nv_bfloat16* lw = hsl + (size_t)((t + 1) & 1) * NB * DD;

        // stage h(t) hi/lo
        for (int idx = tid; idx < 32 * 64; idx += 192) {
            int r = idx >> 6, c = idx & 63;
            cpasync16(smb + 2 * GRUW_B + r * (LDW * 2) + c * 16,
                      hr + (size_t)(mb * 32 + r) * DD + c * 8, 16);
            cpasync16(smb + 2 * GRUW_B + GRUH_B + r * (LDW * 2) + c * 16,
                      lr + (size_t)(mb * 32 + r) * DD + c * 8, 16);
        }
        CP_COMMIT();
        CP_WAIT0();
        __syncthreads();

        float acc0[4] = {0, 0, 0, 0}, acc1[4] = {0, 0, 0, 0};
        #pragma unroll 4
        for (int kc = 0; kc < 32; kc++) {
            uint32_t ah[4], al[4], bh[4], bl[4];
            ldsm_x4(ah, hb_h + kc * 32);
            ldsm_x4(al, hb_l + kc * 32);
            ldsm_x4(bh, wb_h + kc * 32);
            ldsm_x4(bl, wb_l + kc * 32);
            mma16816(acc0, ah, &bh[0]);
            mma16816(acc0, ah, &bl[0]);
            mma16816(acc0, al, &bh[0]);
            mma16816(acc1, ah, &bh[2]);
            mma16816(acc1, ah, &bl[2]);
            mma16816(acc1, al, &bh[2]);
        }

        // prefetch xp(t+1) — off the critical path
        int tn = (t + 1 < NS) ? t + 1 : t;
        fetch_xp(tn, (t + 1) & 1);
        CP_COMMIT();

        // gate slice into gbuf
        {
            int m0 = warp_m * 16 + (lane >> 2);
            int jc = (lane & 3) * 2;
            float* gb = gbuf + (warp_g * 32 + m0) * 16;
            gb[jc] = acc0[0];     gb[jc + 1] = acc0[1];
            gb[jc + 8] = acc1[0]; gb[jc + 9] = acc1[1];
            gb += 8 * 16;
            gb[jc] = acc0[2];     gb[jc + 1] = acc0[3];
            gb[jc + 8] = acc1[2]; gb[jc + 9] = acc1[3];
        }
        __syncthreads();

        // local pointwise (h-state stays in smem)
        float* xb = xsm + (t & 1) * 1536;
        for (int idx = tid; idx < 512; idx += 192) {
            int m_loc = idx >> 4, j_loc = idx & 15;
            int b = mb * 32 + m_loc;
            int j = jBase + j_loc;
            float gr = gbuf[(0 * 32 + m_loc) * 16 + j_loc];
            float gz = gbuf[(1 * 32 + m_loc) * 16 + j_loc];
            float gn = gbuf[(2 * 32 + m_loc) * 16 + j_loc];
            float xr = xb[(0 * 32 + m_loc) * 16 + j_loc];
            float xz = xb[(1 * 32 + m_loc) * 16 + j_loc];
            float xn = xb[(2 * 32 + m_loc) * 16 + j_loc];
            float r = sigmoid_fast(xr + gr + bsm[j_loc]);
            float z = sigmoid_fast(xz + gz + bsm[16 + j_loc]);
            float n = tanh_fast(xn + r * (gn + bsm[32 + j_loc]));
            float hp = hst[idx];
            float h2 = (1.0f - z) * n + z * hp;
            hst[idx] = h2;
            __nv_bfloat16 hb16 = __float2bfloat16_rn(h2);
            __nv_bfloat16 lb16 = __float2bfloat16_rn(h2 - __bfloat162float(hb16));
            hw[(size_t)b * DD + j] = hb16;
            lw[(size_t)b * DD + j] = lb16;
            size_t yi = ((size_t)b * NS + t) * DD + j;
            yh[yi] = hb16;
            yl[yi] = lb16;
            if (wmask && j == 0) maskp[(size_t)b * NS + t] = (h2 != 0.0f) ? 1.0f : 0.0f;
        }
        bar4(mb);
    }

    // write back h-state
    for (int idx = tid; idx < 512; idx += 192) {
        int m_loc = idx >> 4, j_loc = idx & 15;
        hstate[(size_t)(mb * 32 + m_loc) * DD + jBase + j_loc] = hst[idx];
    }
}

extern "C" void kernel_launch(void* const* d_in, const int* in_sizes, int n_in,
                              void* d_out, int out_size) {
    const int*   seqs  = (const int*)d_in[0];
    const float* enc   = (const float*)d_in[2];
    const float* h0    = (const float*)d_in[3];
    const float* emb   = (const float*)d_in[4];
    const float* w_ih  = (const float*)d_in[5];
    const float* w_hh  = (const float*)d_in[6];
    const float* b_ih  = (const float*)d_in[7];
    const float* b_hh  = (const float*)d_in[8];
    const float* attnw = (const float*)d_in[9];
    const float* attnb = (const float*)d_in[10];
    const float* outw  = (const float*)d_in[11];
    const float* outb  = (const float*)d_in[12];
    float* out = (float*)d_out;

    float *xp, *hstate, *mask;
    __nv_bfloat16 *hsh, *hsl, *Ah, *Al, *Ph, *Pl, *Ch, *Cl, *Dh, *Dl;
    __nv_bfloat16 *ench, *encl, *encTh, *encTl, *wihh, *wihl, *whhh, *whhl, *awh, *awl, *owh, *owl;
    cudaGetSymbolAddress((void**)&xp,     g_xp);
    cudaGetSymbolAddress((void**)&hstate, g_h);
    cudaGetSymbolAddress((void**)&mask,   g_mask);
    cudaGetSymbolAddress((void**)&hsh, g_hsh);     cudaGetSymbolAddress((void**)&hsl, g_hsl);
    cudaGetSymbolAddress((void**)&Ah, g_Ah);   cudaGetSymbolAddress((void**)&Al, g_Al);
    cudaGetSymbolAddress((void**)&Ph, g_Ph);   cudaGetSymbolAddress((void**)&Pl, g_Pl);
    cudaGetSymbolAddress((void**)&Ch, g_Ch);   cudaGetSymbolAddress((void**)&Cl, g_Cl);
    cudaGetSymbolAddress((void**)&Dh, g_Dh);   cudaGetSymbolAddress((void**)&Dl, g_Dl);
    cudaGetSymbolAddress((void**)&ench, g_ench);   cudaGetSymbolAddress((void**)&encl, g_encl);
    cudaGetSymbolAddress((void**)&encTh, g_encTh); cudaGetSymbolAddress((void**)&encTl, g_encTl);
    cudaGetSymbolAddress((void**)&wihh, g_wihh);   cudaGetSymbolAddress((void**)&wihl, g_wihl);
    cudaGetSymbolAddress((void**)&whhh, g_whhh);   cudaGetSymbolAddress((void**)&whhl, g_whhl);
    cudaGetSymbolAddress((void**)&awh, g_awh);     cudaGetSymbolAddress((void**)&awl, g_awl);
    cudaGetSymbolAddress((void**)&owh, g_owh);     cudaGetSymbolAddress((void**)&owl, g_owl);

    static int attr_set = 0;
    if (!attr_set) {
        cudaFuncSetAttribute(gru_mma, cudaFuncAttributeMaxDynamicSharedMemorySize, GRU2_SMEM);
        cudaFuncSetAttribute(gemm_mma, cudaFuncAttributeMaxDynamicSharedMemorySize, GM_SMEM);
        attr_set = 1;
    }

    const size_t OUT_H    = (size_t)MALL * NV;
    const size_t OUT_ATTN = OUT_H + (size_t)NL * NB * DD;
    float* attnP = out + OUT_ATTN;
    const float SC = 0.044194173824159216f;

    convert_all<<<(S4 + 255) / 256, 256>>>(
        w_ih, w_hh, attnw, outw, enc,
        wihh, wihl, whhh, whhl, awh, awl, owh, owl, ench, encl);
    transpose_split_kernel<<<dim3(16, 16, 128), dim3(32, 8)>>>(enc, encTh, encTl);
    embed_split_kernel<<<(MALL * (DD / 4)) / 256, 256>>>(seqs, emb, Ah, Al);

    for (int l = 0; l < NL; l++) {
        gemm_mma<<<dim3(12, 512, 1), 256, GM_SMEM>>>(
            Ah, Al, nullptr, nullptr, DD, DD, DD,
            wihh + (size_t)l * D3 * DD, wihl + (size_t)l * D3 * DD, D3,
            xp, nullptr, nullptr, D3, 0, 0, 0, 1.0f, b_ih + (size_t)l * D3, nullptr, 0);
        h_init_kernel<<<(NB * DD / 4 + 255) / 256, 256>>>(
            h0 + (size_t)l * NB * DD, hstate, hsh, hsl);
        gru_mma<<<128, 192, GRU2_SMEM>>>(
            whhh + (size_t)l * D3 * DD, whhl + (size_t)l * D3 * DD,
            b_hh + (size_t)l * D3, xp, hstate, hsh, hsl, Ah, Al, mask,
            (l == NL - 1) ? 1 : 0);
        copy4_kernel<<<64, 256>>>(out + OUT_H + (size_t)l * NB * DD, hstate, NB * DD / 4);
    }

    gemm_mma<<<dim3(4, 4, 128), 256, GM_SMEM>>>(
        Ah, Al, nullptr, nullptr, DD, DD, DD,
        ench, encl, NSE,
        attnP, nullptr, nullptr, NSE, (size_t)NS * DD, (size_t)NSE * DD, (size_t)NS * NSE,
        SC, nullptr, nullptr, 0);
    softmax_kernel<<<MALL, 256>>>(attnP, Ph, Pl);

    gemm_mma<<<dim3(4, 4, 128), 256, GM_SMEM>>>(
        Ph, Pl, nullptr, nullptr, NSE, NSE, NSE,
        encTh, encTl, DD,
        nullptr, Ch, Cl, DD, (size_t)NS * NSE, (size_t)DD * NSE, (size_t)NS * DD,
        1.0f, nullptr, nullptr, 4);

    gemm_mma<<<dim3(4, 512, 1), 256, GM_SMEM>>>(
        Ah, Al, Ch, Cl, DD, DD, 2 * DD,
        awh, awl, DD,
        nullptr, Dh, Dl, DD, 0, 0, 0, 1.0f, attnb, mask, 5);

    gemm_mma<<<dim3(1, 512, 1), 256, GM_SMEM>>>(
        Dh, Dl, nullptr, nullptr, DD, DD, DD,
        owh, owl, NV,
        out, nullptr, nullptr, NV, 0, 0, 0, 1.0f, outb, mask, 2);
}